// round 6
// baseline (speedup 1.0000x reference)
#include <cuda_runtime.h>

#define NU_MAX 100000
#define NI_MAX 50000
#define NER_MAX 1000000
#define NET_MAX 500000
#define EDIM 32

// ---------------- device scratch ----------------
__device__ __align__(256) float g_U0[NU_MAX * EDIM];
__device__ __align__(256) float g_U1[NU_MAX * EDIM];
__device__ __align__(256) float g_U2[NU_MAX * EDIM];
__device__ __align__(256) float g_U3[NU_MAX * EDIM];
__device__ __align__(256) float g_I0[NI_MAX * EDIM];
__device__ __align__(256) float g_I1[NI_MAX * EDIM];
__device__ __align__(256) float g_P1[NI_MAX * EDIM];
__device__ __align__(256) float g_P2[NU_MAX * EDIM];
__device__ __align__(256) float g_H1[NI_MAX * EDIM];
__device__ __align__(256) float g_H2[NU_MAX * EDIM];
__device__ __align__(256) float g_A [NU_MAX * EDIM];
__device__ __align__(256) float g_B [NU_MAX * EDIM];
// CSR structures
__device__ int g_item_cnt[NI_MAX];
__device__ int g_user_cnt[NU_MAX];
__device__ int g_trust_cnt[NU_MAX];
__device__ int g_item_ptr[NI_MAX + 1];
__device__ int g_user_ptr[NU_MAX + 1];
__device__ int g_trust_ptr[NU_MAX + 1];
__device__ int g_item_cur[NI_MAX];
__device__ int g_user_cur[NU_MAX];
__device__ int g_trust_cur[NU_MAX];
__device__ int g_item_adj[NER_MAX];   // for each item row: incident user (rate src)
__device__ int g_user_adj[NER_MAX];   // for each user row: incident item (rate dst)
__device__ int g_trust_adj[NET_MAX];  // for each user row: incident user (trust src)
__device__ float g_stats[64];

__device__ __forceinline__ float lrelu02(float t) { return t > 0.f ? t : 0.2f * t; }

// ---------------- zero counters + stats ----------------
__global__ void zero_kernel(int nu, int ni) {
    int i = blockIdx.x * blockDim.x + threadIdx.x;
    int stride = gridDim.x * blockDim.x;
    for (int k = i; k < nu; k += stride) { g_user_cnt[k] = 0; g_trust_cnt[k] = 0; }
    for (int k = i; k < ni; k += stride) g_item_cnt[k] = 0;
    if (i < 64) g_stats[i] = 0.f;
}

// ---------------- histogram: degree counts for the 3 CSRs ----------------
__global__ void hist_kernel(const int* __restrict__ rsrc, const int* __restrict__ rdst, int ner,
                            const int* __restrict__ tdst, int net) {
    int t = blockIdx.x * blockDim.x + threadIdx.x;
    if (t < ner) {
        atomicAdd(&g_item_cnt[__ldg(&rdst[t])], 1);
        atomicAdd(&g_user_cnt[__ldg(&rsrc[t])], 1);
    } else if (t < ner + net) {
        atomicAdd(&g_trust_cnt[__ldg(&tdst[t - ner])], 1);
    }
}

// ---------------- exclusive scan (3 arrays, one block each) ----------------
__global__ void scan3_kernel(int ni, int nu) {
    int* cnt; int* ptr; int* cur; int n;
    if (blockIdx.x == 0)      { cnt = g_item_cnt;  ptr = g_item_ptr;  cur = g_item_cur;  n = ni; }
    else if (blockIdx.x == 1) { cnt = g_user_cnt;  ptr = g_user_ptr;  cur = g_user_cur;  n = nu; }
    else                      { cnt = g_trust_cnt; ptr = g_trust_ptr; cur = g_trust_cur; n = nu; }

    int tid = threadIdx.x, lane = tid & 31, wid = tid >> 5;
    __shared__ int wsum[32];
    int carry = 0;
    for (int base = 0; base < n; base += 1024) {
        int i = base + tid;
        int v = (i < n) ? cnt[i] : 0;
        int x = v;
#pragma unroll
        for (int off = 1; off < 32; off <<= 1) {
            int t = __shfl_up_sync(0xffffffffu, x, off);
            if (lane >= off) x += t;
        }
        if (lane == 31) wsum[wid] = x;
        __syncthreads();
        if (wid == 0) {
            int y = wsum[lane];
#pragma unroll
            for (int off = 1; off < 32; off <<= 1) {
                int t = __shfl_up_sync(0xffffffffu, y, off);
                if (lane >= off) y += t;
            }
            wsum[lane] = y;
        }
        __syncthreads();
        int woff = wid ? wsum[wid - 1] : 0;
        int excl = x + woff - v;
        if (i < n) { ptr[i] = carry + excl; cur[i] = carry + excl; }
        int total = wsum[31];
        __syncthreads();
        carry += total;
    }
    if (tid == 0) ptr[n] = carry;
}

// ---------------- scatter: fill adjacency lists ----------------
__global__ void scatter_kernel(const int* __restrict__ rsrc, const int* __restrict__ rdst, int ner,
                               const int* __restrict__ tsrc, const int* __restrict__ tdst, int net) {
    int t = blockIdx.x * blockDim.x + threadIdx.x;
    if (t < ner) {
        int s = __ldg(&rsrc[t]);
        int d = __ldg(&rdst[t]);
        int p = atomicAdd(&g_item_cur[d], 1);
        g_item_adj[p] = s;
        int p2 = atomicAdd(&g_user_cur[s], 1);
        g_user_adj[p2] = d;
    } else if (t < ner + net) {
        int s = __ldg(&tsrc[t - ner]);
        int d = __ldg(&tdst[t - ner]);
        int p = atomicAdd(&g_trust_cur[d], 1);
        g_trust_adj[p] = s;
    }
}

// ---------------- quad projection: one input, four weight matrices ----------------
__global__ void proj4_kernel(const float* __restrict__ in,
                             const float* __restrict__ W0, const float* __restrict__ b0,
                             const float* __restrict__ W1, const float* __restrict__ b1,
                             const float* __restrict__ W2, const float* __restrict__ b2,
                             const float* __restrict__ W3, const float* __restrict__ b3,
                             float* __restrict__ O0, float* __restrict__ O1,
                             float* __restrict__ O2, float* __restrict__ O3, int nrows) {
    __shared__ float Wsh[4][32 * 36];
    int tid = threadIdx.x;
    const float* Ws[4] = {W0, W1, W2, W3};
    for (int i = tid; i < 4 * 1024; i += blockDim.x) {
        int m = i >> 10, r = (i >> 5) & 31, c = i & 31;
        Wsh[m][r * 36 + c] = Ws[m][r * 32 + c];
    }
    __syncthreads();
    int warp = tid >> 5, lane = tid & 31;
    int row = blockIdx.x * 8 + warp;
    if (row >= nrows) return;
    float h = in[row * 32 + lane];
    float a0 = b0[lane], a1 = b1[lane], a2 = b2[lane], a3 = b3[lane];
#pragma unroll
    for (int k = 0; k < 32; k += 4) {
        float h0 = __shfl_sync(0xffffffffu, h, k);
        float h1 = __shfl_sync(0xffffffffu, h, k + 1);
        float h2 = __shfl_sync(0xffffffffu, h, k + 2);
        float h3 = __shfl_sync(0xffffffffu, h, k + 3);
        float4 w;
        w = *(const float4*)&Wsh[0][lane * 36 + k]; a0 += h0 * w.x + h1 * w.y + h2 * w.z + h3 * w.w;
        w = *(const float4*)&Wsh[1][lane * 36 + k]; a1 += h0 * w.x + h1 * w.y + h2 * w.z + h3 * w.w;
        w = *(const float4*)&Wsh[2][lane * 36 + k]; a2 += h0 * w.x + h1 * w.y + h2 * w.z + h3 * w.w;
        w = *(const float4*)&Wsh[3][lane * 36 + k]; a3 += h0 * w.x + h1 * w.y + h2 * w.z + h3 * w.w;
    }
    O0[row * 32 + lane] = a0;
    O1[row * 32 + lane] = a1;
    O2[row * 32 + lane] = a2;
    O3[row * 32 + lane] = a3;
}

// ---------------- dual projection: one input, two weight matrices ----------------
__global__ void proj2_kernel(const float* __restrict__ in,
                             const float* __restrict__ W0, const float* __restrict__ b0,
                             const float* __restrict__ W1, const float* __restrict__ b1,
                             float* __restrict__ O0, float* __restrict__ O1, int nrows) {
    __shared__ float Wsh[2][32 * 36];
    int tid = threadIdx.x;
    const float* Ws[2] = {W0, W1};
    for (int i = tid; i < 2 * 1024; i += blockDim.x) {
        int m = i >> 10, r = (i >> 5) & 31, c = i & 31;
        Wsh[m][r * 36 + c] = Ws[m][r * 32 + c];
    }
    __syncthreads();
    int warp = tid >> 5, lane = tid & 31;
    int row = blockIdx.x * 8 + warp;
    if (row >= nrows) return;
    float h = in[row * 32 + lane];
    float a0 = b0[lane], a1 = b1[lane];
#pragma unroll
    for (int k = 0; k < 32; k += 4) {
        float h0 = __shfl_sync(0xffffffffu, h, k);
        float h1 = __shfl_sync(0xffffffffu, h, k + 1);
        float h2 = __shfl_sync(0xffffffffu, h, k + 2);
        float h3 = __shfl_sync(0xffffffffu, h, k + 3);
        float4 w;
        w = *(const float4*)&Wsh[0][lane * 36 + k]; a0 += h0 * w.x + h1 * w.y + h2 * w.z + h3 * w.w;
        w = *(const float4*)&Wsh[1][lane * 36 + k]; a1 += h0 * w.x + h1 * w.y + h2 * w.z + h3 * w.w;
    }
    O0[row * 32 + lane] = a0;
    O1[row * 32 + lane] = a1;
}

// ---------------- two independent projections in one grid (H1->P1, H2->P2) --------
__global__ void projHH_kernel(const float* __restrict__ inA,
                              const float* __restrict__ WA, const float* __restrict__ bA,
                              float* __restrict__ OA, int nA, int nbA,
                              const float* __restrict__ inB,
                              const float* __restrict__ WB, const float* __restrict__ bB,
                              float* __restrict__ OB, int nB) {
    bool second = (int)blockIdx.x >= nbA;
    int b = second ? (int)blockIdx.x - nbA : (int)blockIdx.x;
    const float* in = second ? inB : inA;
    const float* W  = second ? WB : WA;
    const float* bi = second ? bB : bA;
    float* out = second ? OB : OA;
    int nrows = second ? nB : nA;

    __shared__ float Wsh[32 * 36];
    int tid = threadIdx.x;
    for (int i = tid; i < 1024; i += blockDim.x)
        Wsh[(i >> 5) * 36 + (i & 31)] = W[i];
    __syncthreads();
    int warp = tid >> 5, lane = tid & 31;
    int row = b * 8 + warp;
    if (row >= nrows) return;
    float h = in[row * 32 + lane];
    float acc = bi[lane];
#pragma unroll
    for (int k = 0; k < 32; k += 4) {
        float h0 = __shfl_sync(0xffffffffu, h, k);
        float h1 = __shfl_sync(0xffffffffu, h, k + 1);
        float h2 = __shfl_sync(0xffffffffu, h, k + 2);
        float h3 = __shfl_sync(0xffffffffu, h, k + 3);
        float4 w = *(const float4*)&Wsh[lane * 36 + k];
        acc += h0 * w.x + h1 * w.y + h2 * w.z + h3 * w.w;
    }
    out[row * 32 + lane] = acc;
}

// ---------------- CSR aggregation: warp per dst row, 4 edges per pass --------------
// out[d,:] = sum_e exp(score_e) * fs[adj[e],:] / sum_e exp(score_e)
__device__ __forceinline__ void agg_row(
    int d, int lane,
    const int* __restrict__ ptr, const int* __restrict__ adj,
    const float4* __restrict__ fs, const float4* __restrict__ fd,
    const float4* __restrict__ attn, float* __restrict__ out)
{
    int q = lane & 7, g = lane >> 3;
    float4 fd4 = __ldg(&fd[d * 8 + q]);
    float4 a4  = __ldg(&attn[q]);
    int beg = __ldg(&ptr[d]);
    int end = __ldg(&ptr[d + 1]);
    float4 acc = make_float4(0.f, 0.f, 0.f, 0.f);
    float den = 0.f;
    for (int e0 = beg; e0 < end; e0 += 4) {
        int ei = e0 + g;
        bool valid = ei < end;
        int s = __ldg(&adj[valid ? ei : beg]);
        float4 fsv = __ldg(&fs[s * 8 + q]);
        float sc = lrelu02(fsv.x + fd4.x) * a4.x + lrelu02(fsv.y + fd4.y) * a4.y
                 + lrelu02(fsv.z + fd4.z) * a4.z + lrelu02(fsv.w + fd4.w) * a4.w;
        sc += __shfl_xor_sync(0xffffffffu, sc, 1);
        sc += __shfl_xor_sync(0xffffffffu, sc, 2);
        sc += __shfl_xor_sync(0xffffffffu, sc, 4);
        float ex = valid ? __expf(sc) : 0.f;
        acc.x += ex * fsv.x; acc.y += ex * fsv.y;
        acc.z += ex * fsv.z; acc.w += ex * fsv.w;
        den += ex;
    }
    // reduce across the 4 lane-groups
    den   += __shfl_xor_sync(0xffffffffu, den, 8);
    den   += __shfl_xor_sync(0xffffffffu, den, 16);
    acc.x += __shfl_xor_sync(0xffffffffu, acc.x, 8);
    acc.x += __shfl_xor_sync(0xffffffffu, acc.x, 16);
    acc.y += __shfl_xor_sync(0xffffffffu, acc.y, 8);
    acc.y += __shfl_xor_sync(0xffffffffu, acc.y, 16);
    acc.z += __shfl_xor_sync(0xffffffffu, acc.z, 8);
    acc.z += __shfl_xor_sync(0xffffffffu, acc.z, 16);
    acc.w += __shfl_xor_sync(0xffffffffu, acc.w, 8);
    acc.w += __shfl_xor_sync(0xffffffffu, acc.w, 16);
    if (lane < 8) {
        float inv = (den > 0.f) ? (1.0f / den) : 0.f;
        float4 r = make_float4(acc.x * inv, acc.y * inv, acc.z * inv, acc.w * inv);
        ((float4*)out)[d * 8 + q] = r;
    }
}

// two independent aggregations in one grid
__global__ void agg2_kernel(
    const int* __restrict__ ptrA, const int* __restrict__ adjA,
    const float4* __restrict__ fsA, const float4* __restrict__ fdA,
    const float4* __restrict__ atA, float* __restrict__ outA, int nA, int nbA,
    const int* __restrict__ ptrB, const int* __restrict__ adjB,
    const float4* __restrict__ fsB, const float4* __restrict__ fdB,
    const float4* __restrict__ atB, float* __restrict__ outB, int nB)
{
    bool second = (int)blockIdx.x >= nbA;
    int b = second ? (int)blockIdx.x - nbA : (int)blockIdx.x;
    int d = b * 8 + (threadIdx.x >> 5);
    int lane = threadIdx.x & 31;
    if (second) {
        if (d >= nB) return;
        agg_row(d, lane, ptrB, adjB, fsB, fdB, atB, outB);
    } else {
        if (d >= nA) return;
        agg_row(d, lane, ptrA, adjA, fsA, fdA, atA, outA);
    }
}

// ---------------- output head + fused BN stats ----------------
__global__ void head_kernel(const float* __restrict__ A, const float* __restrict__ B,
                            const float* __restrict__ Wout, const float* __restrict__ bout,
                            float* __restrict__ y, int nu) {
    __shared__ float WshA[32 * 36];
    __shared__ float WshB[32 * 36];
    __shared__ float ssum[32], ssq[32];
    int tid = threadIdx.x;
    for (int i = tid; i < 1024; i += blockDim.x) {
        int r = i >> 5, c = i & 31;
        WshA[r * 36 + c] = Wout[r * 64 + c];
        WshB[r * 36 + c] = Wout[r * 64 + 32 + c];
    }
    if (tid < 32) { ssum[tid] = 0.f; ssq[tid] = 0.f; }
    __syncthreads();
    int warp = tid >> 5, lane = tid & 31;
    int row = blockIdx.x * 8 + warp;
    if (row < nu) {
        float av = A[row * 32 + lane];
        float bv = B[row * 32 + lane];
        float acc = bout[lane];
#pragma unroll
        for (int k = 0; k < 32; k += 4) {
            float a0 = __shfl_sync(0xffffffffu, av, k);
            float a1 = __shfl_sync(0xffffffffu, av, k + 1);
            float a2 = __shfl_sync(0xffffffffu, av, k + 2);
            float a3 = __shfl_sync(0xffffffffu, av, k + 3);
            float b0 = __shfl_sync(0xffffffffu, bv, k);
            float b1 = __shfl_sync(0xffffffffu, bv, k + 1);
            float b2 = __shfl_sync(0xffffffffu, bv, k + 2);
            float b3 = __shfl_sync(0xffffffffu, bv, k + 3);
            float4 wa = *(const float4*)&WshA[lane * 36 + k];
            float4 wb = *(const float4*)&WshB[lane * 36 + k];
            acc += a0 * wa.x + a1 * wa.y + a2 * wa.z + a3 * wa.w;
            acc += b0 * wb.x + b1 * wb.y + b2 * wb.z + b3 * wb.w;
        }
        y[row * 32 + lane] = acc;
        atomicAdd(&ssum[lane], acc);
        atomicAdd(&ssq[lane], acc * acc);
    }
    __syncthreads();
    if (tid < 32) {
        atomicAdd(&g_stats[tid], ssum[tid]);
        atomicAdd(&g_stats[32 + tid], ssq[tid]);
    }
}

// ---------------- finalize: BN + LeakyReLU(0.01) ----------------
__global__ void finalize_kernel(float* __restrict__ y, const float* __restrict__ gamma,
                                const float* __restrict__ beta, int nu) {
    int i = blockIdx.x * blockDim.x + threadIdx.x;
    if (i >= nu * 32) return;
    int c = i & 31;
    float inv_n = 1.0f / (float)nu;
    float mean = g_stats[c] * inv_n;
    float var = g_stats[32 + c] * inv_n - mean * mean;
    float v = (y[i] - mean) * rsqrtf(var + 1e-5f) * gamma[c] + beta[c];
    y[i] = (v > 0.f) ? v : 0.01f * v;
}

// ---------------- host launch ----------------
extern "C" void kernel_launch(void* const* d_in, const int* in_sizes, int n_in,
                              void* d_out, int out_size) {
    const float* user = (const float*)d_in[0];
    const float* item = (const float*)d_in[1];
    const int* rate_src  = (const int*)d_in[2];
    const int* rate_dst  = (const int*)d_in[3];
    const int* trust_src = (const int*)d_in[4];
    const int* trust_dst = (const int*)d_in[5];
    const float* p[20];
    for (int i = 0; i < 20; ++i) p[i] = (const float*)d_in[6 + i];
    const float* Wout  = (const float*)d_in[26];
    const float* bout  = (const float*)d_in[27];
    const float* gamma = (const float*)d_in[28];
    const float* beta  = (const float*)d_in[29];

    int nu = in_sizes[0] / EDIM;
    int ni = in_sizes[1] / EDIM;
    int ne_rate  = in_sizes[2];
    int ne_trust = in_sizes[4];
    float* y = (float*)d_out;

    float *U0, *U1, *U2, *U3, *I0, *I1, *P1, *P2, *H1, *H2, *A, *B;
    int *iptr, *uptr, *tptr, *iadj, *uadj, *tadj;
    cudaGetSymbolAddress((void**)&U0, g_U0);
    cudaGetSymbolAddress((void**)&U1, g_U1);
    cudaGetSymbolAddress((void**)&U2, g_U2);
    cudaGetSymbolAddress((void**)&U3, g_U3);
    cudaGetSymbolAddress((void**)&I0, g_I0);
    cudaGetSymbolAddress((void**)&I1, g_I1);
    cudaGetSymbolAddress((void**)&P1, g_P1);
    cudaGetSymbolAddress((void**)&P2, g_P2);
    cudaGetSymbolAddress((void**)&H1, g_H1);
    cudaGetSymbolAddress((void**)&H2, g_H2);
    cudaGetSymbolAddress((void**)&A,  g_A);
    cudaGetSymbolAddress((void**)&B,  g_B);
    cudaGetSymbolAddress((void**)&iptr, g_item_ptr);
    cudaGetSymbolAddress((void**)&uptr, g_user_ptr);
    cudaGetSymbolAddress((void**)&tptr, g_trust_ptr);
    cudaGetSymbolAddress((void**)&iadj, g_item_adj);
    cudaGetSymbolAddress((void**)&uadj, g_user_adj);
    cudaGetSymbolAddress((void**)&tadj, g_trust_adj);

    const int T = 256;
    int gu = (nu + 7) / 8;
    int gi = (ni + 7) / 8;
    int ge_all = (ne_rate + ne_trust + T - 1) / T;

    // ---- CSR build ----
    zero_kernel<<<512, T>>>(nu, ni);
    hist_kernel<<<ge_all, T>>>(rate_src, rate_dst, ne_rate, trust_dst, ne_trust);
    scan3_kernel<<<3, 1024>>>(ni, nu);
    scatter_kernel<<<ge_all, T>>>(rate_src, rate_dst, ne_rate, trust_src, trust_dst, ne_trust);

    // ---- projections ----
    proj4_kernel<<<gu, T>>>(user, p[0], p[1], p[7], p[8], p[12], p[13], p[17], p[18],
                            U0, U1, U2, U3, nu);
    proj2_kernel<<<gi, T>>>(item, p[2], p[3], p[5], p[6], I0, I1, ni);

    // ---- layer 1 aggregation (H1 over items, H2 over users) ----
    agg2_kernel<<<gi + gu, T>>>(
        iptr, iadj, (const float4*)U0, (const float4*)I0, (const float4*)p[4], H1, ni, gi,
        uptr, uadj, (const float4*)I1, (const float4*)U1, (const float4*)p[9], H2, nu);

    // ---- layer 2 source projections ----
    projHH_kernel<<<gi + gu, T>>>(H1, p[10], p[11], P1, ni, gi,
                                  H2, p[15], p[16], P2, nu);

    // ---- layer 2 aggregation (A over users via rate, B over users via trust) ----
    agg2_kernel<<<gu + gu, T>>>(
        uptr, uadj, (const float4*)P1, (const float4*)U2, (const float4*)p[14], A, nu, gu,
        tptr, tadj, (const float4*)P2, (const float4*)U3, (const float4*)p[19], B, nu);

    // ---- head (+fused BN stats) + finalize ----
    head_kernel<<<gu, T>>>(A, B, Wout, bout, y, nu);
    finalize_kernel<<<(nu * EDIM + T - 1) / T, T>>>(y, gamma, beta, nu);
}

// round 7
// speedup vs baseline: 1.1772x; 1.1772x over previous
#include <cuda_runtime.h>

#define NU_MAX 100000
#define NI_MAX 50000
#define EDIM 32

// ---------------- device scratch ----------------
__device__ __align__(256) float g_U0[NU_MAX * EDIM];
__device__ __align__(256) float g_U1[NU_MAX * EDIM];
__device__ __align__(256) float g_U2[NU_MAX * EDIM];
__device__ __align__(256) float g_U3[NU_MAX * EDIM];
__device__ __align__(256) float g_I0[NI_MAX * EDIM];
__device__ __align__(256) float g_I1[NI_MAX * EDIM];
__device__ __align__(256) float g_P1[NI_MAX * EDIM];
__device__ __align__(256) float g_P2[NU_MAX * EDIM];
__device__ __align__(256) float g_H1[NI_MAX * EDIM];
__device__ __align__(256) float g_H2[NU_MAX * EDIM];
__device__ __align__(256) float g_A [NU_MAX * EDIM];
__device__ __align__(256) float g_B [NU_MAX * EDIM];
__device__ float g_S1[NI_MAX];
__device__ float g_S2[NU_MAX];
__device__ float g_S3[NU_MAX];
__device__ float g_S4[NU_MAX];
__device__ float g_stats[64];

__device__ __forceinline__ void red_add_v4(float* p, float4 v) {
    asm volatile("red.global.add.v4.f32 [%0], {%1,%2,%3,%4};"
                 :: "l"(p), "f"(v.x), "f"(v.y), "f"(v.z), "f"(v.w) : "memory");
}
__device__ __forceinline__ float lrelu02(float t) { return t > 0.f ? t : 0.2f * t; }

// ---------------- zero scratch ----------------
__global__ void zero_all_kernel(int nu, int ni) {
    long i0 = (long)blockIdx.x * blockDim.x + threadIdx.x;
    long stride = (long)gridDim.x * blockDim.x;
    long nuE = (long)nu * EDIM, niE = (long)ni * EDIM;
    for (long i = i0; i < nuE; i += stride) { g_H2[i] = 0.f; g_A[i] = 0.f; g_B[i] = 0.f; }
    for (long i = i0; i < niE; i += stride) g_H1[i] = 0.f;
    for (long i = i0; i < nu;  i += stride) { g_S2[i] = 0.f; g_S3[i] = 0.f; g_S4[i] = 0.f; }
    for (long i = i0; i < ni;  i += stride) g_S1[i] = 0.f;
    if (i0 < 64) g_stats[i0] = 0.f;
}

// ---------------- quad projection: one input, four weight matrices ----------------
// Weight tile layout: quad-major float4: WshQ[m][g*32 + lane] = W_m[lane][4g..4g+3]
// 16B-aligned, conflict-free per 8-lane LDS.128 phase.
__global__ void proj4_kernel(const float* __restrict__ in,
                             const float* __restrict__ W0, const float* __restrict__ b0,
                             const float* __restrict__ W1, const float* __restrict__ b1,
                             const float* __restrict__ W2, const float* __restrict__ b2,
                             const float* __restrict__ W3, const float* __restrict__ b3,
                             float* __restrict__ O0, float* __restrict__ O1,
                             float* __restrict__ O2, float* __restrict__ O3, int nrows) {
    __shared__ float4 WshQ[4][256];
    int tid = threadIdx.x;
    const float* Ws[4] = {W0, W1, W2, W3};
    for (int i = tid; i < 1024; i += blockDim.x) {
        int m = i >> 8, rem = i & 255, g = rem >> 5, c = rem & 31;
        WshQ[m][g * 32 + c] = ((const float4*)Ws[m])[c * 8 + g];
    }
    __syncthreads();
    int warp = tid >> 5, lane = tid & 31;
    int row = blockIdx.x * 8 + warp;
    if (row >= nrows) return;
    float h = in[row * 32 + lane];
    float a0 = b0[lane], a1 = b1[lane], a2 = b2[lane], a3 = b3[lane];
#pragma unroll
    for (int g = 0; g < 8; ++g) {
        float h0 = __shfl_sync(0xffffffffu, h, 4 * g);
        float h1 = __shfl_sync(0xffffffffu, h, 4 * g + 1);
        float h2 = __shfl_sync(0xffffffffu, h, 4 * g + 2);
        float h3 = __shfl_sync(0xffffffffu, h, 4 * g + 3);
        float4 w;
        w = WshQ[0][g * 32 + lane]; a0 += h0 * w.x + h1 * w.y + h2 * w.z + h3 * w.w;
        w = WshQ[1][g * 32 + lane]; a1 += h0 * w.x + h1 * w.y + h2 * w.z + h3 * w.w;
        w = WshQ[2][g * 32 + lane]; a2 += h0 * w.x + h1 * w.y + h2 * w.z + h3 * w.w;
        w = WshQ[3][g * 32 + lane]; a3 += h0 * w.x + h1 * w.y + h2 * w.z + h3 * w.w;
    }
    O0[row * 32 + lane] = a0;
    O1[row * 32 + lane] = a1;
    O2[row * 32 + lane] = a2;
    O3[row * 32 + lane] = a3;
}

// ---------------- dual projection ----------------
__global__ void proj2_kernel(const float* __restrict__ in,
                             const float* __restrict__ W0, const float* __restrict__ b0,
                             const float* __restrict__ W1, const float* __restrict__ b1,
                             float* __restrict__ O0, float* __restrict__ O1, int nrows) {
    __shared__ float4 WshQ[2][256];
    int tid = threadIdx.x;
    const float* Ws[2] = {W0, W1};
    for (int i = tid; i < 512; i += blockDim.x) {
        int m = i >> 8, rem = i & 255, g = rem >> 5, c = rem & 31;
        WshQ[m][g * 32 + c] = ((const float4*)Ws[m])[c * 8 + g];
    }
    __syncthreads();
    int warp = tid >> 5, lane = tid & 31;
    int row = blockIdx.x * 8 + warp;
    if (row >= nrows) return;
    float h = in[row * 32 + lane];
    float a0 = b0[lane], a1 = b1[lane];
#pragma unroll
    for (int g = 0; g < 8; ++g) {
        float h0 = __shfl_sync(0xffffffffu, h, 4 * g);
        float h1 = __shfl_sync(0xffffffffu, h, 4 * g + 1);
        float h2 = __shfl_sync(0xffffffffu, h, 4 * g + 2);
        float h3 = __shfl_sync(0xffffffffu, h, 4 * g + 3);
        float4 w;
        w = WshQ[0][g * 32 + lane]; a0 += h0 * w.x + h1 * w.y + h2 * w.z + h3 * w.w;
        w = WshQ[1][g * 32 + lane]; a1 += h0 * w.x + h1 * w.y + h2 * w.z + h3 * w.w;
    }
    O0[row * 32 + lane] = a0;
    O1[row * 32 + lane] = a1;
}

// ---------------- H1/H2 projection (scaled by 1/S), two segments in one grid ------
__global__ void projHH_kernel(const float* __restrict__ inA, const float* __restrict__ sA,
                              const float* __restrict__ WA, const float* __restrict__ bA,
                              float* __restrict__ OA, int nA, int nbA,
                              const float* __restrict__ inB, const float* __restrict__ sB,
                              const float* __restrict__ WB, const float* __restrict__ bB,
                              float* __restrict__ OB, int nB) {
    bool second = (int)blockIdx.x >= nbA;
    int b = second ? (int)blockIdx.x - nbA : (int)blockIdx.x;
    const float* in = second ? inB : inA;
    const float* sd = second ? sB : sA;
    const float* W  = second ? WB : WA;
    const float* bi = second ? bB : bA;
    float* out = second ? OB : OA;
    int nrows = second ? nB : nA;

    __shared__ float4 WshQ[256];
    int tid = threadIdx.x;
    for (int i = tid; i < 256; i += blockDim.x) {
        int g = i >> 5, c = i & 31;
        WshQ[g * 32 + c] = ((const float4*)W)[c * 8 + g];
    }
    __syncthreads();
    int warp = tid >> 5, lane = tid & 31;
    int row = b * 8 + warp;
    if (row >= nrows) return;
    float sv = sd[row];
    float scale = (sv > 0.f) ? (1.0f / sv) : 0.0f;
    float h = in[row * 32 + lane] * scale;
    float acc = bi[lane];
#pragma unroll
    for (int g = 0; g < 8; ++g) {
        float h0 = __shfl_sync(0xffffffffu, h, 4 * g);
        float h1 = __shfl_sync(0xffffffffu, h, 4 * g + 1);
        float h2 = __shfl_sync(0xffffffffu, h, 4 * g + 2);
        float h3 = __shfl_sync(0xffffffffu, h, 4 * g + 3);
        float4 w = WshQ[g * 32 + lane];
        acc += h0 * w.x + h1 * w.y + h2 * w.z + h3 * w.w;
    }
    out[row * 32 + lane] = acc;
}

// ---------------- core edge step: 8 lanes per edge, float4 channels ----------------
__device__ __forceinline__ void edge_step(
    int si, int di, int q, bool valid,
    const float4* __restrict__ fs, const float4* __restrict__ fd,
    const float4* __restrict__ attn, float* __restrict__ out, float* __restrict__ den)
{
    float4 fsv = __ldg(&fs[si * 8 + q]);
    float4 fdv = __ldg(&fd[di * 8 + q]);
    float4 a = __ldg(&attn[q]);
    float s = lrelu02(fsv.x + fdv.x) * a.x + lrelu02(fsv.y + fdv.y) * a.y
            + lrelu02(fsv.z + fdv.z) * a.z + lrelu02(fsv.w + fdv.w) * a.w;
    s += __shfl_xor_sync(0xffffffffu, s, 1);
    s += __shfl_xor_sync(0xffffffffu, s, 2);
    s += __shfl_xor_sync(0xffffffffu, s, 4);
    float ex = __expf(s);
    if (valid) {
        float4 r = make_float4(ex * fsv.x, ex * fsv.y, ex * fsv.z, ex * fsv.w);
        red_add_v4(&out[di * 32 + q * 4], r);
        if (q == 0) atomicAdd(&den[di], ex);
    }
}

// ---------------- layer-1 fused: both directions, 2 edges per thread (ILP 4) -------
__global__ void edge_l1_kernel(const int* __restrict__ src, const int* __restrict__ dst,
                               const float4* __restrict__ fsA, const float4* __restrict__ fdA,
                               const float4* __restrict__ attnA, float* __restrict__ outA, float* __restrict__ denA,
                               const float4* __restrict__ fsB, const float4* __restrict__ fdB,
                               const float4* __restrict__ attnB, float* __restrict__ outB, float* __restrict__ denB,
                               int ne, int half) {
    int t = blockIdx.x * blockDim.x + threadIdx.x;
    int e0 = t >> 3;
    int q = t & 7;
    int e1 = e0 + half;
    bool v0 = e0 < ne;
    bool v1 = e1 < ne;
    int c0 = v0 ? e0 : 0;
    int c1 = v1 ? e1 : 0;
    int u0 = __ldg(&src[c0]), w0 = __ldg(&dst[c0]);
    int u1 = __ldg(&src[c1]), w1 = __ldg(&dst[c1]);
    edge_step(u0, w0, q, v0, fsA, fdA, attnA, outA, denA);  // user -> item ('rate')
    edge_step(u1, w1, q, v1, fsA, fdA, attnA, outA, denA);
    edge_step(w0, u0, q, v0, fsB, fdB, attnB, outB, denB);  // item -> user ('rated-by')
    edge_step(w1, u1, q, v1, fsB, fdB, attnB, outB, denB);
}

// ---------------- layer-2: rby (2 edges/thread) + trust (1 edge/thread) ------------
__global__ void edge_l2_kernel(
    const int* __restrict__ s1, const int* __restrict__ d1,
    const float4* __restrict__ fs1, const float4* __restrict__ fd1,
    const float4* __restrict__ a1, float* __restrict__ o1, float* __restrict__ den1,
    int ne1, int half1,
    const int* __restrict__ s2, const int* __restrict__ d2,
    const float4* __restrict__ fs2, const float4* __restrict__ fd2,
    const float4* __restrict__ a2, float* __restrict__ o2, float* __restrict__ den2,
    int ne2)
{
    int t = blockIdx.x * blockDim.x + threadIdx.x;
    int e0 = t >> 3;
    int q = t & 7;
    int e1 = e0 + half1;
    bool v0 = e0 < ne1;
    bool v1 = e1 < ne1;
    bool v2 = e0 < ne2;
    int c0 = v0 ? e0 : 0;
    int c1 = v1 ? e1 : 0;
    int c2 = v2 ? e0 : 0;
    int u0 = __ldg(&s1[c0]), w0 = __ldg(&d1[c0]);
    int u1 = __ldg(&s1[c1]), w1 = __ldg(&d1[c1]);
    int u2 = __ldg(&s2[c2]), w2 = __ldg(&d2[c2]);
    edge_step(u0, w0, q, v0, fs1, fd1, a1, o1, den1);
    edge_step(u1, w1, q, v1, fs1, fd1, a1, o1, den1);
    edge_step(u2, w2, q, v2, fs2, fd2, a2, o2, den2);
}

// ---------------- output head + fused BN stats ----------------
__global__ void head_kernel(const float* __restrict__ A, const float* __restrict__ B,
                            const float* __restrict__ s3, const float* __restrict__ s4,
                            const float* __restrict__ Wout, const float* __restrict__ bout,
                            float* __restrict__ y, int nu) {
    __shared__ float4 WshA[256];   // A half:  Wout[c][4g..4g+3]
    __shared__ float4 WshB[256];   // B half:  Wout[c][32+4g..32+4g+3]
    __shared__ float ssum[32], ssq[32];
    int tid = threadIdx.x;
    for (int i = tid; i < 256; i += blockDim.x) {
        int g = i >> 5, c = i & 31;
        WshA[g * 32 + c] = ((const float4*)Wout)[c * 16 + g];
        WshB[g * 32 + c] = ((const float4*)Wout)[c * 16 + 8 + g];
    }
    if (tid < 32) { ssum[tid] = 0.f; ssq[tid] = 0.f; }
    __syncthreads();
    int warp = tid >> 5, lane = tid & 31;
    int row = blockIdx.x * 8 + warp;
    if (row < nu) {
        float sa = s3[row]; sa = (sa > 0.f) ? (1.0f / sa) : 0.0f;
        float sb = s4[row]; sb = (sb > 0.f) ? (1.0f / sb) : 0.0f;
        float av = A[row * 32 + lane] * sa;
        float bv = B[row * 32 + lane] * sb;
        float acc = bout[lane];
#pragma unroll
        for (int g = 0; g < 8; ++g) {
            float a0 = __shfl_sync(0xffffffffu, av, 4 * g);
            float a1 = __shfl_sync(0xffffffffu, av, 4 * g + 1);
            float a2 = __shfl_sync(0xffffffffu, av, 4 * g + 2);
            float a3 = __shfl_sync(0xffffffffu, av, 4 * g + 3);
            float b0 = __shfl_sync(0xffffffffu, bv, 4 * g);
            float b1 = __shfl_sync(0xffffffffu, bv, 4 * g + 1);
            float b2 = __shfl_sync(0xffffffffu, bv, 4 * g + 2);
            float b3 = __shfl_sync(0xffffffffu, bv, 4 * g + 3);
            float4 wa = WshA[g * 32 + lane];
            float4 wb = WshB[g * 32 + lane];
            acc += a0 * wa.x + a1 * wa.y + a2 * wa.z + a3 * wa.w;
            acc += b0 * wb.x + b1 * wb.y + b2 * wb.z + b3 * wb.w;
        }
        y[row * 32 + lane] = acc;
        atomicAdd(&ssum[lane], acc);
        atomicAdd(&ssq[lane], acc * acc);
    }
    __syncthreads();
    if (tid < 32) {
        atomicAdd(&g_stats[tid], ssum[tid]);
        atomicAdd(&g_stats[32 + tid], ssq[tid]);
    }
}

// ---------------- finalize: BN + LeakyReLU(0.01) ----------------
__global__ void finalize_kernel(float* __restrict__ y, const float* __restrict__ gamma,
                                const float* __restrict__ beta, int nu) {
    int i = blockIdx.x * blockDim.x + threadIdx.x;
    if (i >= nu * 32) return;
    int c = i & 31;
    float inv_n = 1.0f / (float)nu;
    float mean = g_stats[c] * inv_n;
    float var = g_stats[32 + c] * inv_n - mean * mean;
    float v = (y[i] - mean) * rsqrtf(var + 1e-5f) * gamma[c] + beta[c];
    y[i] = (v > 0.f) ? v : 0.01f * v;
}

// ---------------- host launch ----------------
extern "C" void kernel_launch(void* const* d_in, const int* in_sizes, int n_in,
                              void* d_out, int out_size) {
    const float* user = (const float*)d_in[0];
    const float* item = (const float*)d_in[1];
    const int* rate_src  = (const int*)d_in[2];
    const int* rate_dst  = (const int*)d_in[3];
    const int* trust_src = (const int*)d_in[4];
    const int* trust_dst = (const int*)d_in[5];
    const float* p[20];
    for (int i = 0; i < 20; ++i) p[i] = (const float*)d_in[6 + i];
    const float* Wout  = (const float*)d_in[26];
    const float* bout  = (const float*)d_in[27];
    const float* gamma = (const float*)d_in[28];
    const float* beta  = (const float*)d_in[29];

    int nu = in_sizes[0] / EDIM;
    int ni = in_sizes[1] / EDIM;
    int ne_rate  = in_sizes[2];
    int ne_trust = in_sizes[4];
    float* y = (float*)d_out;

    float *U0, *U1, *U2, *U3, *I0, *I1, *P1, *P2, *H1, *H2, *A, *B, *S1, *S2, *S3, *S4;
    cudaGetSymbolAddress((void**)&U0, g_U0);
    cudaGetSymbolAddress((void**)&U1, g_U1);
    cudaGetSymbolAddress((void**)&U2, g_U2);
    cudaGetSymbolAddress((void**)&U3, g_U3);
    cudaGetSymbolAddress((void**)&I0, g_I0);
    cudaGetSymbolAddress((void**)&I1, g_I1);
    cudaGetSymbolAddress((void**)&P1, g_P1);
    cudaGetSymbolAddress((void**)&P2, g_P2);
    cudaGetSymbolAddress((void**)&H1, g_H1);
    cudaGetSymbolAddress((void**)&H2, g_H2);
    cudaGetSymbolAddress((void**)&A,  g_A);
    cudaGetSymbolAddress((void**)&B,  g_B);
    cudaGetSymbolAddress((void**)&S1, g_S1);
    cudaGetSymbolAddress((void**)&S2, g_S2);
    cudaGetSymbolAddress((void**)&S3, g_S3);
    cudaGetSymbolAddress((void**)&S4, g_S4);

    const int T = 256;
    int gu = (nu + 7) / 8;
    int gi = (ni + 7) / 8;
    int half_r = (ne_rate + 1) / 2;
    int gb_l1 = (half_r * 8 + T - 1) / T;
    int slots_l2 = (half_r > ne_trust) ? half_r : ne_trust;
    int gb_l2 = (slots_l2 * 8 + T - 1) / T;

    zero_all_kernel<<<2048, T>>>(nu, ni);

    // all user projections in one pass, all item projections in one pass
    proj4_kernel<<<gu, T>>>(user, p[0], p[1], p[7], p[8], p[12], p[13], p[17], p[18],
                            U0, U1, U2, U3, nu);
    proj2_kernel<<<gi, T>>>(item, p[2], p[3], p[5], p[6], I0, I1, ni);

    // layer 1 fused edge pass (rate + rated-by share the edge list), 2 edges/thread
    edge_l1_kernel<<<gb_l1, T>>>(rate_src, rate_dst,
                                 (const float4*)U0, (const float4*)I0, (const float4*)p[4], H1, S1,
                                 (const float4*)I1, (const float4*)U1, (const float4*)p[9], H2, S2,
                                 ne_rate, half_r);

    // layer-2 src projections (normalization folded via S1/S2), both in one grid
    projHH_kernel<<<gi + gu, T>>>(H1, S1, p[10], p[11], P1, ni, gi,
                                  H2, S2, p[15], p[16], P2, nu);

    // layer-2 edge pass: rby (2 edges/thread) + trust (1 edge/thread)
    edge_l2_kernel<<<gb_l2, T>>>(
        rate_dst, rate_src, (const float4*)P1, (const float4*)U2, (const float4*)p[14], A, S3,
        ne_rate, half_r,
        trust_src, trust_dst, (const float4*)P2, (const float4*)U3, (const float4*)p[19], B, S4,
        ne_trust);

    // head (+fused BN stats) + finalize
    head_kernel<<<gu, T>>>(A, B, S3, S4, Wout, bout, y, nu);
    finalize_kernel<<<(nu * EDIM + T - 1) / T, T>>>(y, gamma, beta, nu);
}

// round 8
// speedup vs baseline: 1.3547x; 1.1508x over previous
#include <cuda_runtime.h>

#define NU_MAX 100000
#define NI_MAX 50000
#define EDIM 32

// ---------------- device scratch ----------------
__device__ __align__(256) float g_U0[NU_MAX * EDIM];
__device__ __align__(256) float g_U1[NU_MAX * EDIM];
__device__ __align__(256) float g_U2[NU_MAX * EDIM];
__device__ __align__(256) float g_U3[NU_MAX * EDIM];
__device__ __align__(256) float g_I0[NI_MAX * EDIM];
__device__ __align__(256) float g_I1[NI_MAX * EDIM];
__device__ __align__(256) float g_P1[NI_MAX * EDIM];
__device__ __align__(256) float g_P2[NU_MAX * EDIM];
__device__ __align__(256) float g_H1[NI_MAX * EDIM];
__device__ __align__(256) float g_H2[NU_MAX * EDIM];
__device__ __align__(256) float g_A [NU_MAX * EDIM];
__device__ __align__(256) float g_B [NU_MAX * EDIM];
__device__ float g_S1[NI_MAX];
__device__ float g_S2[NU_MAX];
__device__ float g_S3[NU_MAX];
__device__ float g_S4[NU_MAX];
__device__ float g_stats[64];

__device__ __forceinline__ void red_add_v4(float* p, float4 v) {
    asm volatile("red.global.add.v4.f32 [%0], {%1,%2,%3,%4};"
                 :: "l"(p), "f"(v.x), "f"(v.y), "f"(v.z), "f"(v.w) : "memory");
}
__device__ __forceinline__ float lrelu02(float t) { return t > 0.f ? t : 0.2f * t; }

// ---------------- zero scratch ----------------
__global__ void zero_all_kernel(int nu, int ni) {
    long i0 = (long)blockIdx.x * blockDim.x + threadIdx.x;
    long stride = (long)gridDim.x * blockDim.x;
    long nuE = (long)nu * EDIM, niE = (long)ni * EDIM;
    for (long i = i0; i < nuE; i += stride) { g_H2[i] = 0.f; g_A[i] = 0.f; g_B[i] = 0.f; }
    for (long i = i0; i < niE; i += stride) g_H1[i] = 0.f;
    for (long i = i0; i < nu;  i += stride) { g_S2[i] = 0.f; g_S3[i] = 0.f; g_S4[i] = 0.f; }
    for (long i = i0; i < ni;  i += stride) g_S1[i] = 0.f;
    if (i0 < 64) g_stats[i0] = 0.f;
}

// ---------------- fused projections: user x4 matrices, item x2, one grid ----------
// smem layout per matrix: Wsh[r*36 + c] (aligned: 36*4=144=9*16; float4 LDS conflict-free)
__global__ void proj_all_kernel(const float* __restrict__ user,
                                const float* __restrict__ W0, const float* __restrict__ b0,
                                const float* __restrict__ W1, const float* __restrict__ b1,
                                const float* __restrict__ W2, const float* __restrict__ b2,
                                const float* __restrict__ W3, const float* __restrict__ b3,
                                float* __restrict__ O0, float* __restrict__ O1,
                                float* __restrict__ O2, float* __restrict__ O3,
                                int nu, int nbu,
                                const float* __restrict__ item,
                                const float* __restrict__ V0, const float* __restrict__ c0,
                                const float* __restrict__ V1, const float* __restrict__ c1,
                                float* __restrict__ Q0, float* __restrict__ Q1, int ni) {
    __shared__ float Wsh[4][32 * 36];
    int tid = threadIdx.x;
    bool second = (int)blockIdx.x >= nbu;
    int b = second ? (int)blockIdx.x - nbu : (int)blockIdx.x;
    int nmat = second ? 2 : 4;
    const float* Ws[4];
    if (second) { Ws[0] = V0; Ws[1] = V1; Ws[2] = V0; Ws[3] = V1; }
    else        { Ws[0] = W0; Ws[1] = W1; Ws[2] = W2; Ws[3] = W3; }
    for (int i = tid; i < nmat * 1024; i += blockDim.x) {
        int m = i >> 10, r = (i >> 5) & 31, c = i & 31;
        Wsh[m][r * 36 + c] = Ws[m][r * 32 + c];
    }
    __syncthreads();
    int warp = tid >> 5, lane = tid & 31;
    int row = b * 8 + warp;
    if (second) {
        if (row >= ni) return;
        float h = item[row * 32 + lane];
        float a0 = c0[lane], a1 = c1[lane];
#pragma unroll
        for (int k = 0; k < 32; k += 4) {
            float h0 = __shfl_sync(0xffffffffu, h, k);
            float h1 = __shfl_sync(0xffffffffu, h, k + 1);
            float h2 = __shfl_sync(0xffffffffu, h, k + 2);
            float h3 = __shfl_sync(0xffffffffu, h, k + 3);
            float4 w;
            w = *(const float4*)&Wsh[0][lane * 36 + k]; a0 += h0 * w.x + h1 * w.y + h2 * w.z + h3 * w.w;
            w = *(const float4*)&Wsh[1][lane * 36 + k]; a1 += h0 * w.x + h1 * w.y + h2 * w.z + h3 * w.w;
        }
        Q0[row * 32 + lane] = a0;
        Q1[row * 32 + lane] = a1;
    } else {
        if (row >= nu) return;
        float h = user[row * 32 + lane];
        float a0 = b0[lane], a1 = b1[lane], a2 = b2[lane], a3 = b3[lane];
#pragma unroll
        for (int k = 0; k < 32; k += 4) {
            float h0 = __shfl_sync(0xffffffffu, h, k);
            float h1 = __shfl_sync(0xffffffffu, h, k + 1);
            float h2 = __shfl_sync(0xffffffffu, h, k + 2);
            float h3 = __shfl_sync(0xffffffffu, h, k + 3);
            float4 w;
            w = *(const float4*)&Wsh[0][lane * 36 + k]; a0 += h0 * w.x + h1 * w.y + h2 * w.z + h3 * w.w;
            w = *(const float4*)&Wsh[1][lane * 36 + k]; a1 += h0 * w.x + h1 * w.y + h2 * w.z + h3 * w.w;
            w = *(const float4*)&Wsh[2][lane * 36 + k]; a2 += h0 * w.x + h1 * w.y + h2 * w.z + h3 * w.w;
            w = *(const float4*)&Wsh[3][lane * 36 + k]; a3 += h0 * w.x + h1 * w.y + h2 * w.z + h3 * w.w;
        }
        O0[row * 32 + lane] = a0;
        O1[row * 32 + lane] = a1;
        O2[row * 32 + lane] = a2;
        O3[row * 32 + lane] = a3;
    }
}

// ---------------- H1/H2 projection (scaled by 1/S), two segments in one grid ------
__global__ void projHH_kernel(const float* __restrict__ inA, const float* __restrict__ sA,
                              const float* __restrict__ WA, const float* __restrict__ bA,
                              float* __restrict__ OA, int nA, int nbA,
                              const float* __restrict__ inB, const float* __restrict__ sB,
                              const float* __restrict__ WB, const float* __restrict__ bB,
                              float* __restrict__ OB, int nB) {
    bool second = (int)blockIdx.x >= nbA;
    int b = second ? (int)blockIdx.x - nbA : (int)blockIdx.x;
    const float* in = second ? inB : inA;
    const float* sd = second ? sB : sA;
    const float* W  = second ? WB : WA;
    const float* bi = second ? bB : bA;
    float* out = second ? OB : OA;
    int nrows = second ? nB : nA;

    __shared__ float Wsh[32 * 36];
    int tid = threadIdx.x;
    for (int i = tid; i < 1024; i += blockDim.x)
        Wsh[(i >> 5) * 36 + (i & 31)] = W[i];
    __syncthreads();
    int warp = tid >> 5, lane = tid & 31;
    int row = b * 8 + warp;
    if (row >= nrows) return;
    float sv = sd[row];
    float scale = (sv > 0.f) ? (1.0f / sv) : 0.0f;
    float h = in[row * 32 + lane] * scale;
    float acc = bi[lane];
#pragma unroll
    for (int k = 0; k < 32; k += 4) {
        float h0 = __shfl_sync(0xffffffffu, h, k);
        float h1 = __shfl_sync(0xffffffffu, h, k + 1);
        float h2 = __shfl_sync(0xffffffffu, h, k + 2);
        float h3 = __shfl_sync(0xffffffffu, h, k + 3);
        float4 w = *(const float4*)&Wsh[lane * 36 + k];
        acc += h0 * w.x + h1 * w.y + h2 * w.z + h3 * w.w;
    }
    out[row * 32 + lane] = acc;
}

// ---------------- core edge step: 8 lanes per edge, float4 channels ----------------
__device__ __forceinline__ void edge_step(
    int si, int di, int q, bool valid,
    const float4* __restrict__ fs, const float4* __restrict__ fd,
    float4 a, float* __restrict__ out, float* __restrict__ den)
{
    float4 fsv = __ldg(&fs[si * 8 + q]);
    float4 fdv = __ldg(&fd[di * 8 + q]);
    float s = lrelu02(fsv.x + fdv.x) * a.x + lrelu02(fsv.y + fdv.y) * a.y
            + lrelu02(fsv.z + fdv.z) * a.z + lrelu02(fsv.w + fdv.w) * a.w;
    s += __shfl_xor_sync(0xffffffffu, s, 1);
    s += __shfl_xor_sync(0xffffffffu, s, 2);
    s += __shfl_xor_sync(0xffffffffu, s, 4);
    float ex = __expf(s);
    if (valid) {
        float4 r = make_float4(ex * fsv.x, ex * fsv.y, ex * fsv.z, ex * fsv.w);
        red_add_v4(&out[di * 32 + q * 4], r);
        if (q == 0) atomicAdd(&den[di], ex);
    }
}

// ---------------- layer-1 fused: both directions, 2 edges per thread (ILP 4) -------
__global__ void edge_l1_kernel(const int* __restrict__ src, const int* __restrict__ dst,
                               const float4* __restrict__ fsA, const float4* __restrict__ fdA,
                               const float4* __restrict__ attnA, float* __restrict__ outA, float* __restrict__ denA,
                               const float4* __restrict__ fsB, const float4* __restrict__ fdB,
                               const float4* __restrict__ attnB, float* __restrict__ outB, float* __restrict__ denB,
                               int ne, int half) {
    int t = blockIdx.x * blockDim.x + threadIdx.x;
    int e0 = t >> 3;
    int q = t & 7;
    float4 aA = __ldg(&attnA[q]);
    float4 aB = __ldg(&attnB[q]);
    int e1 = e0 + half;
    bool v0 = e0 < ne;
    bool v1 = e1 < ne;
    int c0 = v0 ? e0 : 0;
    int c1 = v1 ? e1 : 0;
    int u0 = __ldg(&src[c0]), w0 = __ldg(&dst[c0]);
    int u1 = __ldg(&src[c1]), w1 = __ldg(&dst[c1]);
    edge_step(u0, w0, q, v0, fsA, fdA, aA, outA, denA);  // user -> item ('rate')
    edge_step(u1, w1, q, v1, fsA, fdA, aA, outA, denA);
    edge_step(w0, u0, q, v0, fsB, fdB, aB, outB, denB);  // item -> user ('rated-by')
    edge_step(w1, u1, q, v1, fsB, fdB, aB, outB, denB);
}

// ---------------- layer-2: rby (2 edges/thread) + trust (1 edge/thread) ------------
__global__ void edge_l2_kernel(
    const int* __restrict__ s1, const int* __restrict__ d1,
    const float4* __restrict__ fs1, const float4* __restrict__ fd1,
    const float4* __restrict__ a1, float* __restrict__ o1, float* __restrict__ den1,
    int ne1, int half1,
    const int* __restrict__ s2, const int* __restrict__ d2,
    const float4* __restrict__ fs2, const float4* __restrict__ fd2,
    const float4* __restrict__ a2, float* __restrict__ o2, float* __restrict__ den2,
    int ne2)
{
    int t = blockIdx.x * blockDim.x + threadIdx.x;
    int e0 = t >> 3;
    int q = t & 7;
    float4 aa1 = __ldg(&a1[q]);
    float4 aa2 = __ldg(&a2[q]);
    int e1 = e0 + half1;
    bool v0 = e0 < ne1;
    bool v1 = e1 < ne1;
    bool v2 = e0 < ne2;
    int c0 = v0 ? e0 : 0;
    int c1 = v1 ? e1 : 0;
    int c2 = v2 ? e0 : 0;
    int u0 = __ldg(&s1[c0]), w0 = __ldg(&d1[c0]);
    int u1 = __ldg(&s1[c1]), w1 = __ldg(&d1[c1]);
    int u2 = __ldg(&s2[c2]), w2 = __ldg(&d2[c2]);
    edge_step(u0, w0, q, v0, fs1, fd1, aa1, o1, den1);
    edge_step(u1, w1, q, v1, fs1, fd1, aa1, o1, den1);
    edge_step(u2, w2, q, v2, fs2, fd2, aa2, o2, den2);
}

// ---------------- output head + fused BN stats ----------------
__global__ void head_kernel(const float* __restrict__ A, const float* __restrict__ B,
                            const float* __restrict__ s3, const float* __restrict__ s4,
                            const float* __restrict__ Wout, const float* __restrict__ bout,
                            float* __restrict__ y, int nu) {
    __shared__ float WshA[32 * 36];   // Wout[out][0..31]
    __shared__ float WshB[32 * 36];   // Wout[out][32..63]
    __shared__ float ssum[32], ssq[32];
    int tid = threadIdx.x;
    for (int i = tid; i < 1024; i += blockDim.x) {
        int r = i >> 5, c = i & 31;
        WshA[r * 36 + c] = Wout[r * 64 + c];
        WshB[r * 36 + c] = Wout[r * 64 + 32 + c];
    }
    if (tid < 32) { ssum[tid] = 0.f; ssq[tid] = 0.f; }
    __syncthreads();
    int warp = tid >> 5, lane = tid & 31;
    int row = blockIdx.x * 8 + warp;
    if (row < nu) {
        float sa = s3[row]; sa = (sa > 0.f) ? (1.0f / sa) : 0.0f;
        float sb = s4[row]; sb = (sb > 0.f) ? (1.0f / sb) : 0.0f;
        float av = A[row * 32 + lane] * sa;
        float bv = B[row * 32 + lane] * sb;
        float acc = bout[lane];
#pragma unroll
        for (int k = 0; k < 32; k += 4) {
            float a0 = __shfl_sync(0xffffffffu, av, k);
            float a1 = __shfl_sync(0xffffffffu, av, k + 1);
            float a2 = __shfl_sync(0xffffffffu, av, k + 2);
            float a3 = __shfl_sync(0xffffffffu, av, k + 3);
            float b0 = __shfl_sync(0xffffffffu, bv, k);
            float b1 = __shfl_sync(0xffffffffu, bv, k + 1);
            float b2 = __shfl_sync(0xffffffffu, bv, k + 2);
            float b3 = __shfl_sync(0xffffffffu, bv, k + 3);
            float4 wa = *(const float4*)&WshA[lane * 36 + k];
            float4 wb = *(const float4*)&WshB[lane * 36 + k];
            acc += a0 * wa.x + a1 * wa.y + a2 * wa.z + a3 * wa.w;
            acc += b0 * wb.x + b1 * wb.y + b2 * wb.z + b3 * wb.w;
        }
        y[row * 32 + lane] = acc;
        atomicAdd(&ssum[lane], acc);
        atomicAdd(&ssq[lane], acc * acc);
    }
    __syncthreads();
    if (tid < 32) {
        atomicAdd(&g_stats[tid], ssum[tid]);
        atomicAdd(&g_stats[32 + tid], ssq[tid]);
    }
}

// ---------------- finalize: BN + LeakyReLU(0.01) ----------------
__global__ void finalize_kernel(float* __restrict__ y, const float* __restrict__ gamma,
                                const float* __restrict__ beta, int nu) {
    int i = blockIdx.x * blockDim.x + threadIdx.x;
    if (i >= nu * 32) return;
    int c = i & 31;
    float inv_n = 1.0f / (float)nu;
    float mean = g_stats[c] * inv_n;
    float var = g_stats[32 + c] * inv_n - mean * mean;
    float v = (y[i] - mean) * rsqrtf(var + 1e-5f) * gamma[c] + beta[c];
    y[i] = (v > 0.f) ? v : 0.01f * v;
}

// ---------------- host launch ----------------
extern "C" void kernel_launch(void* const* d_in, const int* in_sizes, int n_in,
                              void* d_out, int out_size) {
    const float* user = (const float*)d_in[0];
    const float* item = (const float*)d_in[1];
    const int* rate_src  = (const int*)d_in[2];
    const int* rate_dst  = (const int*)d_in[3];
    const int* trust_src = (const int*)d_in[4];
    const int* trust_dst = (const int*)d_in[5];
    const float* p[20];
    for (int i = 0; i < 20; ++i) p[i] = (const float*)d_in[6 + i];
    const float* Wout  = (const float*)d_in[26];
    const float* bout  = (const float*)d_in[27];
    const float* gamma = (const float*)d_in[28];
    const float* beta  = (const float*)d_in[29];

    int nu = in_sizes[0] / EDIM;
    int ni = in_sizes[1] / EDIM;
    int ne_rate  = in_sizes[2];
    int ne_trust = in_sizes[4];
    float* y = (float*)d_out;

    float *U0, *U1, *U2, *U3, *I0, *I1, *P1, *P2, *H1, *H2, *A, *B, *S1, *S2, *S3, *S4;
    cudaGetSymbolAddress((void**)&U0, g_U0);
    cudaGetSymbolAddress((void**)&U1, g_U1);
    cudaGetSymbolAddress((void**)&U2, g_U2);
    cudaGetSymbolAddress((void**)&U3, g_U3);
    cudaGetSymbolAddress((void**)&I0, g_I0);
    cudaGetSymbolAddress((void**)&I1, g_I1);
    cudaGetSymbolAddress((void**)&P1, g_P1);
    cudaGetSymbolAddress((void**)&P2, g_P2);
    cudaGetSymbolAddress((void**)&H1, g_H1);
    cudaGetSymbolAddress((void**)&H2, g_H2);
    cudaGetSymbolAddress((void**)&A,  g_A);
    cudaGetSymbolAddress((void**)&B,  g_B);
    cudaGetSymbolAddress((void**)&S1, g_S1);
    cudaGetSymbolAddress((void**)&S2, g_S2);
    cudaGetSymbolAddress((void**)&S3, g_S3);
    cudaGetSymbolAddress((void**)&S4, g_S4);

    const int T = 256;
    int gu = (nu + 7) / 8;
    int gi = (ni + 7) / 8;
    int half_r = (ne_rate + 1) / 2;
    int gb_l1 = (half_r * 8 + T - 1) / T;
    int slots_l2 = (half_r > ne_trust) ? half_r : ne_trust;
    int gb_l2 = (slots_l2 * 8 + T - 1) / T;

    zero_all_kernel<<<2048, T>>>(nu, ni);

    // all 6 input projections in one segmented launch
    proj_all_kernel<<<gu + gi, T>>>(user, p[0], p[1], p[7], p[8], p[12], p[13], p[17], p[18],
                                    U0, U1, U2, U3, nu, gu,
                                    item, p[2], p[3], p[5], p[6], I0, I1, ni);

    // layer 1 fused edge pass (rate + rated-by share the edge list), 2 edges/thread
    edge_l1_kernel<<<gb_l1, T>>>(rate_src, rate_dst,
                                 (const float4*)U0, (const float4*)I0, (const float4*)p[4], H1, S1,
                                 (const float4*)I1, (const float4*)U1, (const float4*)p[9], H2, S2,
                                 ne_rate, half_r);

    // layer-2 src projections (normalization folded via S1/S2), both in one grid
    projHH_kernel<<<gi + gu, T>>>(H1, S1, p[10], p[11], P1, ni, gi,
                                  H2, S2, p[15], p[16], P2, nu);

    // layer-2 edge pass: rby (2 edges/thread) + trust (1 edge/thread)
    edge_l2_kernel<<<gb_l2, T>>>(
        rate_dst, rate_src, (const float4*)P1, (const float4*)U2, (const float4*)p[14], A, S3,
        ne_rate, half_r,
        trust_src, trust_dst, (const float4*)P2, (const float4*)U3, (const float4*)p[19], B, S4,
        ne_trust);

    // head (+fused BN stats) + finalize
    head_kernel<<<gu, T>>>(A, B, S3, S4, Wout, bout, y, nu);
    finalize_kernel<<<(nu * EDIM + T - 1) / T, T>>>(y, gamma, beta, nu);
}

// round 10
// speedup vs baseline: 1.5516x; 1.1454x over previous
#include <cuda_runtime.h>

#define NU_MAX 100000
#define NI_MAX 50000
#define EDIM 32

// ---------------- device scratch ----------------
__device__ __align__(256) float g_U0[NU_MAX * EDIM];
__device__ __align__(256) float g_U1[NU_MAX * EDIM];
__device__ __align__(256) float g_U2[NU_MAX * EDIM];
__device__ __align__(256) float g_U3[NU_MAX * EDIM];
__device__ __align__(256) float g_I0[NI_MAX * EDIM];
__device__ __align__(256) float g_I1[NI_MAX * EDIM];
__device__ __align__(256) float g_P1[NI_MAX * EDIM];
__device__ __align__(256) float g_P2[NU_MAX * EDIM];
__device__ __align__(256) float g_H1[NI_MAX * EDIM];
__device__ __align__(256) float g_H2[NU_MAX * EDIM];
__device__ __align__(256) float g_A [NU_MAX * EDIM];
__device__ __align__(256) float g_B [NU_MAX * EDIM];
__device__ float g_S1[NI_MAX];
__device__ float g_S2[NU_MAX];
__device__ float g_S3[NU_MAX];
__device__ float g_S4[NU_MAX];
__device__ float g_stats[64];

__device__ __forceinline__ void red_add_v4(float* p, float4 v) {
    asm volatile("red.global.add.v4.f32 [%0], {%1,%2,%3,%4};"
                 :: "l"(p), "f"(v.x), "f"(v.y), "f"(v.z), "f"(v.w) : "memory");
}
__device__ __forceinline__ float lrelu02(float t) { return t > 0.f ? t : 0.2f * t; }

// ---------------- zero scratch ----------------
__global__ void zero_all_kernel(int nu, int ni) {
    long i0 = (long)blockIdx.x * blockDim.x + threadIdx.x;
    long stride = (long)gridDim.x * blockDim.x;
    long nuE = (long)nu * EDIM, niE = (long)ni * EDIM;
    for (long i = i0; i < nuE; i += stride) { g_H2[i] = 0.f; g_A[i] = 0.f; g_B[i] = 0.f; }
    for (long i = i0; i < niE; i += stride) g_H1[i] = 0.f;
    for (long i = i0; i < nu;  i += stride) { g_S2[i] = 0.f; g_S3[i] = 0.f; g_S4[i] = 0.f; }
    for (long i = i0; i < ni;  i += stride) g_S1[i] = 0.f;
    if (i0 < 64) g_stats[i0] = 0.f;
}

// ---------------- fused projections, persistent: user x4 + item x2 ----------------
// smem layout per matrix: Wsh[r*36 + c] (36*4=144 bytes: float4 loads aligned, conflict-free)
__global__ void proj_all_kernel(const float* __restrict__ user,
                                const float* __restrict__ W0, const float* __restrict__ b0,
                                const float* __restrict__ W1, const float* __restrict__ b1,
                                const float* __restrict__ W2, const float* __restrict__ b2,
                                const float* __restrict__ W3, const float* __restrict__ b3,
                                float* __restrict__ O0, float* __restrict__ O1,
                                float* __restrict__ O2, float* __restrict__ O3,
                                int nu, int nbu,
                                const float* __restrict__ item,
                                const float* __restrict__ V0, const float* __restrict__ c0,
                                const float* __restrict__ V1, const float* __restrict__ c1,
                                float* __restrict__ Q0, float* __restrict__ Q1, int ni) {
    __shared__ float Wsh[4][32 * 36];
    int tid = threadIdx.x;
    bool second = (int)blockIdx.x >= nbu;
    int b = second ? (int)blockIdx.x - nbu : (int)blockIdx.x;
    int nblk = second ? (int)gridDim.x - nbu : nbu;
    int nmat = second ? 2 : 4;
    const float* Ws[4];
    if (second) { Ws[0] = V0; Ws[1] = V1; Ws[2] = V0; Ws[3] = V1; }
    else        { Ws[0] = W0; Ws[1] = W1; Ws[2] = W2; Ws[3] = W3; }
    for (int i = tid; i < nmat * 1024; i += blockDim.x) {
        int m = i >> 10, r = (i >> 5) & 31, c = i & 31;
        Wsh[m][r * 36 + c] = Ws[m][r * 32 + c];
    }
    __syncthreads();
    int warp = tid >> 5, lane = tid & 31;
    int rstep = nblk * 8;
    if (second) {
        float a0b = c0[lane], a1b = c1[lane];
        for (int row = b * 8 + warp; row < ni; row += rstep) {
            float h = item[row * 32 + lane];
            float a0 = a0b, a1 = a1b;
#pragma unroll
            for (int k = 0; k < 32; k += 4) {
                float h0 = __shfl_sync(0xffffffffu, h, k);
                float h1 = __shfl_sync(0xffffffffu, h, k + 1);
                float h2 = __shfl_sync(0xffffffffu, h, k + 2);
                float h3 = __shfl_sync(0xffffffffu, h, k + 3);
                float4 w;
                w = *(const float4*)&Wsh[0][lane * 36 + k]; a0 += h0 * w.x + h1 * w.y + h2 * w.z + h3 * w.w;
                w = *(const float4*)&Wsh[1][lane * 36 + k]; a1 += h0 * w.x + h1 * w.y + h2 * w.z + h3 * w.w;
            }
            Q0[row * 32 + lane] = a0;
            Q1[row * 32 + lane] = a1;
        }
    } else {
        float b0v = b0[lane], b1v = b1[lane], b2v = b2[lane], b3v = b3[lane];
        for (int row = b * 8 + warp; row < nu; row += rstep) {
            float h = user[row * 32 + lane];
            float a0 = b0v, a1 = b1v, a2 = b2v, a3 = b3v;
#pragma unroll
            for (int k = 0; k < 32; k += 4) {
                float h0 = __shfl_sync(0xffffffffu, h, k);
                float h1 = __shfl_sync(0xffffffffu, h, k + 1);
                float h2 = __shfl_sync(0xffffffffu, h, k + 2);
                float h3 = __shfl_sync(0xffffffffu, h, k + 3);
                float4 w;
                w = *(const float4*)&Wsh[0][lane * 36 + k]; a0 += h0 * w.x + h1 * w.y + h2 * w.z + h3 * w.w;
                w = *(const float4*)&Wsh[1][lane * 36 + k]; a1 += h0 * w.x + h1 * w.y + h2 * w.z + h3 * w.w;
                w = *(const float4*)&Wsh[2][lane * 36 + k]; a2 += h0 * w.x + h1 * w.y + h2 * w.z + h3 * w.w;
                w = *(const float4*)&Wsh[3][lane * 36 + k]; a3 += h0 * w.x + h1 * w.y + h2 * w.z + h3 * w.w;
            }
            O0[row * 32 + lane] = a0;
            O1[row * 32 + lane] = a1;
            O2[row * 32 + lane] = a2;
            O3[row * 32 + lane] = a3;
        }
    }
}

// ---------------- H1/H2 projection (scaled by 1/S), persistent, two segments ------
__global__ void projHH_kernel(const float* __restrict__ inA, const float* __restrict__ sA,
                              const float* __restrict__ WA, const float* __restrict__ bA,
                              float* __restrict__ OA, int nA, int nbA,
                              const float* __restrict__ inB, const float* __restrict__ sB,
                              const float* __restrict__ WB, const float* __restrict__ bB,
                              float* __restrict__ OB, int nB) {
    bool second = (int)blockIdx.x >= nbA;
    int b = second ? (int)blockIdx.x - nbA : (int)blockIdx.x;
    int nblk = second ? (int)gridDim.x - nbA : nbA;
    const float* in = second ? inB : inA;
    const float* sd = second ? sB : sA;
    const float* W  = second ? WB : WA;
    const float* bi = second ? bB : bA;
    float* out = second ? OB : OA;
    int nrows = second ? nB : nA;

    __shared__ float Wsh[32 * 36];
    int tid = threadIdx.x;
    for (int i = tid; i < 1024; i += blockDim.x)
        Wsh[(i >> 5) * 36 + (i & 31)] = W[i];
    __syncthreads();
    int warp = tid >> 5, lane = tid & 31;
    float bias = bi[lane];
    int rstep = nblk * 8;
    for (int row = b * 8 + warp; row < nrows; row += rstep) {
        float sv = sd[row];
        float scale = (sv > 0.f) ? (1.0f / sv) : 0.0f;
        float h = in[row * 32 + lane] * scale;
        float acc = bias;
#pragma unroll
        for (int k = 0; k < 32; k += 4) {
            float h0 = __shfl_sync(0xffffffffu, h, k);
            float h1 = __shfl_sync(0xffffffffu, h, k + 1);
            float h2 = __shfl_sync(0xffffffffu, h, k + 2);
            float h3 = __shfl_sync(0xffffffffu, h, k + 3);
            float4 w = *(const float4*)&Wsh[lane * 36 + k];
            acc += h0 * w.x + h1 * w.y + h2 * w.z + h3 * w.w;
        }
        out[row * 32 + lane] = acc;
    }
}

// ---------------- core edge step: 8 lanes per edge, float4 channels ----------------
__device__ __forceinline__ void edge_step(
    int si, int di, int q, bool valid,
    const float4* __restrict__ fs, const float4* __restrict__ fd,
    float4 a, float* __restrict__ out, float* __restrict__ den)
{
    float4 fsv = __ldg(&fs[si * 8 + q]);
    float4 fdv = __ldg(&fd[di * 8 + q]);
    float s = lrelu02(fsv.x + fdv.x) * a.x + lrelu02(fsv.y + fdv.y) * a.y
            + lrelu02(fsv.z + fdv.z) * a.z + lrelu02(fsv.w + fdv.w) * a.w;
    s += __shfl_xor_sync(0xffffffffu, s, 1);
    s += __shfl_xor_sync(0xffffffffu, s, 2);
    s += __shfl_xor_sync(0xffffffffu, s, 4);
    float ex = __expf(s);
    if (valid) {
        float4 r = make_float4(ex * fsv.x, ex * fsv.y, ex * fsv.z, ex * fsv.w);
        red_add_v4(&out[di * 32 + q * 4], r);
        if (q == 0) atomicAdd(&den[di], ex);
    }
}

// ---------------- layer-1 fused: both directions, 2 edges per thread (ILP 4) -------
__global__ void edge_l1_kernel(const int* __restrict__ src, const int* __restrict__ dst,
                               const float4* __restrict__ fsA, const float4* __restrict__ fdA,
                               const float4* __restrict__ attnA, float* __restrict__ outA, float* __restrict__ denA,
                               const float4* __restrict__ fsB, const float4* __restrict__ fdB,
                               const float4* __restrict__ attnB, float* __restrict__ outB, float* __restrict__ denB,
                               int ne, int half) {
    int t = blockIdx.x * blockDim.x + threadIdx.x;
    int e0 = t >> 3;
    int q = t & 7;
    float4 aA = __ldg(&attnA[q]);
    float4 aB = __ldg(&attnB[q]);
    int e1 = e0 + half;
    bool v0 = e0 < ne;
    bool v1 = e1 < ne;
    int c0 = v0 ? e0 : 0;
    int c1 = v1 ? e1 : 0;
    int u0 = __ldg(&src[c0]), w0 = __ldg(&dst[c0]);
    int u1 = __ldg(&src[c1]), w1 = __ldg(&dst[c1]);
    edge_step(u0, w0, q, v0, fsA, fdA, aA, outA, denA);  // user -> item ('rate')
    edge_step(u1, w1, q, v1, fsA, fdA, aA, outA, denA);
    edge_step(w0, u0, q, v0, fsB, fdB, aB, outB, denB);  // item -> user ('rated-by')
    edge_step(w1, u1, q, v1, fsB, fdB, aB, outB, denB);
}

// ---------------- layer-2: rby (2 edges/thread) + trust (1 edge/thread) ------------
__global__ void edge_l2_kernel(
    const int* __restrict__ s1, const int* __restrict__ d1,
    const float4* __restrict__ fs1, const float4* __restrict__ fd1,
    const float4* __restrict__ a1, float* __restrict__ o1, float* __restrict__ den1,
    int ne1, int half1,
    const int* __restrict__ s2, const int* __restrict__ d2,
    const float4* __restrict__ fs2, const float4* __restrict__ fd2,
    const float4* __restrict__ a2, float* __restrict__ o2, float* __restrict__ den2,
    int ne2)
{
    int t = blockIdx.x * blockDim.x + threadIdx.x;
    int e0 = t >> 3;
    int q = t & 7;
    float4 aa1 = __ldg(&a1[q]);
    float4 aa2 = __ldg(&a2[q]);
    int e1 = e0 + half1;
    bool v0 = e0 < ne1;
    bool v1 = e1 < ne1;
    bool v2 = e0 < ne2;
    int c0 = v0 ? e0 : 0;
    int c1 = v1 ? e1 : 0;
    int c2 = v2 ? e0 : 0;
    int u0 = __ldg(&s1[c0]), w0 = __ldg(&d1[c0]);
    int u1 = __ldg(&s1[c1]), w1 = __ldg(&d1[c1]);
    int u2 = __ldg(&s2[c2]), w2 = __ldg(&d2[c2]);
    edge_step(u0, w0, q, v0, fs1, fd1, aa1, o1, den1);
    edge_step(u1, w1, q, v1, fs1, fd1, aa1, o1, den1);
    edge_step(u2, w2, q, v2, fs2, fd2, aa2, o2, den2);
}

// ---------------- output head + fused BN stats, persistent ----------------
__global__ void head_kernel(const float* __restrict__ A, const float* __restrict__ B,
                            const float* __restrict__ s3, const float* __restrict__ s4,
                            const float* __restrict__ Wout, const float* __restrict__ bout,
                            float* __restrict__ y, int nu) {
    __shared__ float WshA[32 * 36];   // Wout[out][0..31]
    __shared__ float WshB[32 * 36];   // Wout[out][32..63]
    __shared__ float ssum[32], ssq[32];
    int tid = threadIdx.x;
    for (int i = tid; i < 1024; i += blockDim.x) {
        int r = i >> 5, c = i & 31;
        WshA[r * 36 + c] = Wout[r * 64 + c];
        WshB[r * 36 + c] = Wout[r * 64 + 32 + c];
    }
    if (tid < 32) { ssum[tid] = 0.f; ssq[tid] = 0.f; }
    __syncthreads();
    int warp = tid >> 5, lane = tid & 31;
    float bias = bout[lane];
    float lsum = 0.f, lsq = 0.f;
    int rstep = gridDim.x * 8;
    for (int row = blockIdx.x * 8 + warp; row < nu; row += rstep) {
        float sa = s3[row]; sa = (sa > 0.f) ? (1.0f / sa) : 0.0f;
        float sb = s4[row]; sb = (sb > 0.f) ? (1.0f / sb) : 0.0f;
        float av = A[row * 32 + lane] * sa;
        float bv = B[row * 32 + lane] * sb;
        float acc = bias;
#pragma unroll
        for (int k = 0; k < 32; k += 4) {
            float a0 = __shfl_sync(0xffffffffu, av, k);
            float a1 = __shfl_sync(0xffffffffu, av, k + 1);
            float a2 = __shfl_sync(0xffffffffu, av, k + 2);
            float a3 = __shfl_sync(0xffffffffu, av, k + 3);
            float b0 = __shfl_sync(0xffffffffu, bv, k);
            float b1 = __shfl_sync(0xffffffffu, bv, k + 1);
            float b2 = __shfl_sync(0xffffffffu, bv, k + 2);
            float b3 = __shfl_sync(0xffffffffu, bv, k + 3);
            float4 wa = *(const float4*)&WshA[lane * 36 + k];
            float4 wb = *(const float4*)&WshB[lane * 36 + k];
            acc += a0 * wa.x + a1 * wa.y + a2 * wa.z + a3 * wa.w;
            acc += b0 * wb.x + b1 * wb.y + b2 * wb.z + b3 * wb.w;
        }
        y[row * 32 + lane] = acc;
        lsum += acc;
        lsq += acc * acc;
    }
    atomicAdd(&ssum[lane], lsum);
    atomicAdd(&ssq[lane], lsq);
    __syncthreads();
    if (tid < 32) {
        atomicAdd(&g_stats[tid], ssum[tid]);
        atomicAdd(&g_stats[32 + tid], ssq[tid]);
    }
}

// ---------------- finalize: BN + LeakyReLU(0.01) ----------------
__global__ void finalize_kernel(float* __restrict__ y, const float* __restrict__ gamma,
                                const float* __restrict__ beta, int nu) {
    int i = blockIdx.x * blockDim.x + threadIdx.x;
    if (i >= nu * 32) return;
    int c = i & 31;
    float inv_n = 1.0f / (float)nu;
    float mean = g_stats[c] * inv_n;
    float var = g_stats[32 + c] * inv_n - mean * mean;
    float v = (y[i] - mean) * rsqrtf(var + 1e-5f) * gamma[c] + beta[c];
    y[i] = (v > 0.f) ? v : 0.01f * v;
}

// ---------------- host launch ----------------
extern "C" void kernel_launch(void* const* d_in, const int* in_sizes, int n_in,
                              void* d_out, int out_size) {
    const float* user = (const float*)d_in[0];
    const float* item = (const float*)d_in[1];
    const int* rate_src  = (const int*)d_in[2];
    const int* rate_dst  = (const int*)d_in[3];
    const int* trust_src = (const int*)d_in[4];
    const int* trust_dst = (const int*)d_in[5];
    const float* p[20];
    for (int i = 0; i < 20; ++i) p[i] = (const float*)d_in[6 + i];
    const float* Wout  = (const float*)d_in[26];
    const float* bout  = (const float*)d_in[27];
    const float* gamma = (const float*)d_in[28];
    const float* beta  = (const float*)d_in[29];

    int nu = in_sizes[0] / EDIM;
    int ni = in_sizes[1] / EDIM;
    int ne_rate  = in_sizes[2];
    int ne_trust = in_sizes[4];
    float* y = (float*)d_out;

    float *U0, *U1, *U2, *U3, *I0, *I1, *P1, *P2, *H1, *H2, *A, *B, *S1, *S2, *S3, *S4;
    cudaGetSymbolAddress((void**)&U0, g_U0);
    cudaGetSymbolAddress((void**)&U1, g_U1);
    cudaGetSymbolAddress((void**)&U2, g_U2);
    cudaGetSymbolAddress((void**)&U3, g_U3);
    cudaGetSymbolAddress((void**)&I0, g_I0);
    cudaGetSymbolAddress((void**)&I1, g_I1);
    cudaGetSymbolAddress((void**)&P1, g_P1);
    cudaGetSymbolAddress((void**)&P2, g_P2);
    cudaGetSymbolAddress((void**)&H1, g_H1);
    cudaGetSymbolAddress((void**)&H2, g_H2);
    cudaGetSymbolAddress((void**)&A,  g_A);
    cudaGetSymbolAddress((void**)&B,  g_B);
    cudaGetSymbolAddress((void**)&S1, g_S1);
    cudaGetSymbolAddress((void**)&S2, g_S2);
    cudaGetSymbolAddress((void**)&S3, g_S3);
    cudaGetSymbolAddress((void**)&S4, g_S4);

    const int T = 256;
    int half_r = (ne_rate + 1) / 2;
    int gb_l1 = (half_r * 8 + T - 1) / T;
    int slots_l2 = (half_r > ne_trust) ? half_r : ne_trust;
    int gb_l2 = (slots_l2 * 8 + T - 1) / T;

    // persistent block counts (multiples of SM count 148)
    const int NBU = 592;   // user segment of proj_all (4 waves)
    const int NBI = 296;   // item segment of proj_all
    const int NBA = 296;   // projHH segment A (ni rows)
    const int NBB = 592;   // projHH segment B (nu rows)
    const int NBH = 592;   // head

    zero_all_kernel<<<2048, T>>>(nu, ni);

    // all 6 input projections in one persistent segmented launch
    proj_all_kernel<<<NBU + NBI, T>>>(user, p[0], p[1], p[7], p[8], p[12], p[13], p[17], p[18],
                                      U0, U1, U2, U3, nu, NBU,
                                      item, p[2], p[3], p[5], p[6], I0, I1, ni);

    // layer 1 fused edge pass (rate + rated-by share the edge list), 2 edges/thread
    edge_l1_kernel<<<gb_l1, T>>>(rate_src, rate_dst,
                                 (const float4*)U0, (const float4*)I0, (const float4*)p[4], H1, S1,
                                 (const float4*)I1, (const float4*)U1, (const float4*)p[9], H2, S2,
                                 ne_rate, half_r);

    // layer-2 src projections (normalization folded via S1/S2), persistent
    projHH_kernel<<<NBA + NBB, T>>>(H1, S1, p[10], p[11], P1, ni, NBA,
                                    H2, S2, p[15], p[16], P2, nu);

    // layer-2 edge pass: rby (2 edges/thread) + trust (1 edge/thread)
    edge_l2_kernel<<<gb_l2, T>>>(
        rate_dst, rate_src, (const float4*)P1, (const float4*)U2, (const float4*)p[14], A, S3,
        ne_rate, half_r,
        trust_src, trust_dst, (const float4*)P2, (const float4*)U3, (const float4*)p[19], B, S4,
        ne_trust);

    // head (+fused BN stats) + finalize
    head_kernel<<<NBH, T>>>(A, B, S3, S4, Wout, bout, y, nu);
    finalize_kernel<<<(nu * EDIM + T - 1) / T, T>>>(y, gamma, beta, nu);
}

// round 12
// speedup vs baseline: 1.5850x; 1.0215x over previous
#include <cuda_runtime.h>

#define NU_MAX 100000
#define NI_MAX 50000
#define EDIM 32

// ---------------- device scratch ----------------
__device__ __align__(256) float g_U0[NU_MAX * EDIM];
__device__ __align__(256) float g_U1[NU_MAX * EDIM];
__device__ __align__(256) float g_U2[NU_MAX * EDIM];
__device__ __align__(256) float g_U3[NU_MAX * EDIM];
__device__ __align__(256) float g_I0[NI_MAX * EDIM];
__device__ __align__(256) float g_I1[NI_MAX * EDIM];
__device__ __align__(256) float g_P1[NI_MAX * EDIM];
__device__ __align__(256) float g_P2[NU_MAX * EDIM];
__device__ __align__(256) float g_H1[NI_MAX * EDIM];
__device__ __align__(256) float g_H2[NU_MAX * EDIM];
__device__ __align__(256) float g_A [NU_MAX * EDIM];
__device__ __align__(256) float g_B [NU_MAX * EDIM];
__device__ float g_S1[NI_MAX];
__device__ float g_S2[NU_MAX];
__device__ float g_S3[NU_MAX];
__device__ float g_S4[NU_MAX];
__device__ float g_stats[64];

__device__ __forceinline__ void red_add_v4(float* p, float4 v) {
    asm volatile("red.global.add.v4.f32 [%0], {%1,%2,%3,%4};"
                 :: "l"(p), "f"(v.x), "f"(v.y), "f"(v.z), "f"(v.w) : "memory");
}
__device__ __forceinline__ float lrelu02(float t) { return t > 0.f ? t : 0.2f * t; }

// ---------------- fused projections, persistent: user x4 + item x2 ----------------
// Also zeroes ALL accumulation scratch (H1/H2/A/B, S1..S4, stats) before its GEMM
// loop — kernel-boundary ordering guarantees consumers see zeroed buffers.
// smem layout per matrix: Wsh[r*36 + c] (36*4=144 bytes: float4 loads aligned, conflict-free)
__global__ void proj_all_kernel(const float* __restrict__ user,
                                const float* __restrict__ W0, const float* __restrict__ b0,
                                const float* __restrict__ W1, const float* __restrict__ b1,
                                const float* __restrict__ W2, const float* __restrict__ b2,
                                const float* __restrict__ W3, const float* __restrict__ b3,
                                float* __restrict__ O0, float* __restrict__ O1,
                                float* __restrict__ O2, float* __restrict__ O3,
                                int nu, int nbu,
                                const float* __restrict__ item,
                                const float* __restrict__ V0, const float* __restrict__ c0,
                                const float* __restrict__ V1, const float* __restrict__ c1,
                                float* __restrict__ Q0, float* __restrict__ Q1, int ni) {
    __shared__ float Wsh[4][32 * 36];
    int tid = threadIdx.x;

    // ---- integrated scratch zeroing (grid-stride, float4) ----
    {
        long i0 = (long)blockIdx.x * blockDim.x + tid;
        long stride = (long)gridDim.x * blockDim.x;
        long nuQ = (long)nu * 8, niQ = (long)ni * 8;   // float4 counts
        float4 z4 = make_float4(0.f, 0.f, 0.f, 0.f);
        for (long i = i0; i < nuQ; i += stride) {
            ((float4*)g_H2)[i] = z4;
            ((float4*)g_A)[i]  = z4;
            ((float4*)g_B)[i]  = z4;
        }
        for (long i = i0; i < niQ; i += stride) ((float4*)g_H1)[i] = z4;
        for (long i = i0; i < nu;  i += stride) { g_S2[i] = 0.f; g_S3[i] = 0.f; g_S4[i] = 0.f; }
        for (long i = i0; i < ni;  i += stride) g_S1[i] = 0.f;
        if (i0 < 64) g_stats[i0] = 0.f;
    }

    bool second = (int)blockIdx.x >= nbu;
    int b = second ? (int)blockIdx.x - nbu : (int)blockIdx.x;
    int nblk = second ? (int)gridDim.x - nbu : nbu;
    int nmat = second ? 2 : 4;
    const float* Ws[4];
    if (second) { Ws[0] = V0; Ws[1] = V1; Ws[2] = V0; Ws[3] = V1; }
    else        { Ws[0] = W0; Ws[1] = W1; Ws[2] = W2; Ws[3] = W3; }
    for (int i = tid; i < nmat * 1024; i += blockDim.x) {
        int m = i >> 10, r = (i >> 5) & 31, c = i & 31;
        Wsh[m][r * 36 + c] = Ws[m][r * 32 + c];
    }
    __syncthreads();
    int warp = tid >> 5, lane = tid & 31;
    int rstep = nblk * 8;
    if (second) {
        float a0b = c0[lane], a1b = c1[lane];
        for (int row = b * 8 + warp; row < ni; row += rstep) {
            float h = item[row * 32 + lane];
            float a0 = a0b, a1 = a1b;
#pragma unroll
            for (int k = 0; k < 32; k += 4) {
                float h0 = __shfl_sync(0xffffffffu, h, k);
                float h1 = __shfl_sync(0xffffffffu, h, k + 1);
                float h2 = __shfl_sync(0xffffffffu, h, k + 2);
                float h3 = __shfl_sync(0xffffffffu, h, k + 3);
                float4 w;
                w = *(const float4*)&Wsh[0][lane * 36 + k]; a0 += h0 * w.x + h1 * w.y + h2 * w.z + h3 * w.w;
                w = *(const float4*)&Wsh[1][lane * 36 + k]; a1 += h0 * w.x + h1 * w.y + h2 * w.z + h3 * w.w;
            }
            Q0[row * 32 + lane] = a0;
            Q1[row * 32 + lane] = a1;
        }
    } else {
        float b0v = b0[lane], b1v = b1[lane], b2v = b2[lane], b3v = b3[lane];
        for (int row = b * 8 + warp; row < nu; row += rstep) {
            float h = user[row * 32 + lane];
            float a0 = b0v, a1 = b1v, a2 = b2v, a3 = b3v;
#pragma unroll
            for (int k = 0; k < 32; k += 4) {
                float h0 = __shfl_sync(0xffffffffu, h, k);
                float h1 = __shfl_sync(0xffffffffu, h, k + 1);
                float h2 = __shfl_sync(0xffffffffu, h, k + 2);
                float h3 = __shfl_sync(0xffffffffu, h, k + 3);
                float4 w;
                w = *(const float4*)&Wsh[0][lane * 36 + k]; a0 += h0 * w.x + h1 * w.y + h2 * w.z + h3 * w.w;
                w = *(const float4*)&Wsh[1][lane * 36 + k]; a1 += h0 * w.x + h1 * w.y + h2 * w.z + h3 * w.w;
                w = *(const float4*)&Wsh[2][lane * 36 + k]; a2 += h0 * w.x + h1 * w.y + h2 * w.z + h3 * w.w;
                w = *(const float4*)&Wsh[3][lane * 36 + k]; a3 += h0 * w.x + h1 * w.y + h2 * w.z + h3 * w.w;
            }
            O0[row * 32 + lane] = a0;
            O1[row * 32 + lane] = a1;
            O2[row * 32 + lane] = a2;
            O3[row * 32 + lane] = a3;
        }
    }
}

// ---------------- H1/H2 projection (scaled by 1/S), persistent, two segments ------
__global__ void projHH_kernel(const float* __restrict__ inA, const float* __restrict__ sA,
                              const float* __restrict__ WA, const float* __restrict__ bA,
                              float* __restrict__ OA, int nA, int nbA,
                              const float* __restrict__ inB, const float* __restrict__ sB,
                              const float* __restrict__ WB, const float* __restrict__ bB,
                              float* __restrict__ OB, int nB) {
    bool second = (int)blockIdx.x >= nbA;
    int b = second ? (int)blockIdx.x - nbA : (int)blockIdx.x;
    int nblk = second ? (int)gridDim.x - nbA : nbA;
    const float* in = second ? inB : inA;
    const float* sd = second ? sB : sA;
    const float* W  = second ? WB : WA;
    const float* bi = second ? bB : bA;
    float* out = second ? OB : OA;
    int nrows = second ? nB : nA;

    __shared__ float Wsh[32 * 36];
    int tid = threadIdx.x;
    for (int i = tid; i < 1024; i += blockDim.x)
        Wsh[(i >> 5) * 36 + (i & 31)] = W[i];
    __syncthreads();
    int warp = tid >> 5, lane = tid & 31;
    float bias = bi[lane];
    int rstep = nblk * 8;
    for (int row = b * 8 + warp; row < nrows; row += rstep) {
        float sv = sd[row];
        float scale = (sv > 0.f) ? (1.0f / sv) : 0.0f;
        float h = in[row * 32 + lane] * scale;
        float acc = bias;
#pragma unroll
        for (int k = 0; k < 32; k += 4) {
            float h0 = __shfl_sync(0xffffffffu, h, k);
            float h1 = __shfl_sync(0xffffffffu, h, k + 1);
            float h2 = __shfl_sync(0xffffffffu, h, k + 2);
            float h3 = __shfl_sync(0xffffffffu, h, k + 3);
            float4 w = *(const float4*)&Wsh[lane * 36 + k];
            acc += h0 * w.x + h1 * w.y + h2 * w.z + h3 * w.w;
        }
        out[row * 32 + lane] = acc;
    }
}

// ---------------- core edge step: 8 lanes per edge, float4 channels ----------------
__device__ __forceinline__ void edge_step(
    int si, int di, int q, bool valid,
    const float4* __restrict__ fs, const float4* __restrict__ fd,
    float4 a, float* __restrict__ out, float* __restrict__ den)
{
    float4 fsv = __ldg(&fs[si * 8 + q]);
    float4 fdv = __ldg(&fd[di * 8 + q]);
    float s = lrelu02(fsv.x + fdv.x) * a.x + lrelu02(fsv.y + fdv.y) * a.y
            + lrelu02(fsv.z + fdv.z) * a.z + lrelu02(fsv.w + fdv.w) * a.w;
    s += __shfl_xor_sync(0xffffffffu, s, 1);
    s += __shfl_xor_sync(0xffffffffu, s, 2);
    s += __shfl_xor_sync(0xffffffffu, s, 4);
    float ex = __expf(s);
    if (valid) {
        float4 r = make_float4(ex * fsv.x, ex * fsv.y, ex * fsv.z, ex * fsv.w);
        red_add_v4(&out[di * 32 + q * 4], r);
        if (q == 0) atomicAdd(&den[di], ex);
    }
}

// ---------------- layer-1 fused: both directions, 2 edges per thread (ILP 4) -------
__global__ void edge_l1_kernel(const int* __restrict__ src, const int* __restrict__ dst,
                               const float4* __restrict__ fsA, const float4* __restrict__ fdA,
                               const float4* __restrict__ attnA, float* __restrict__ outA, float* __restrict__ denA,
                               const float4* __restrict__ fsB, const float4* __restrict__ fdB,
                               const float4* __restrict__ attnB, float* __restrict__ outB, float* __restrict__ denB,
                               int ne, int half) {
    int t = blockIdx.x * blockDim.x + threadIdx.x;
    int e0 = t >> 3;
    int q = t & 7;
    float4 aA = __ldg(&attnA[q]);
    float4 aB = __ldg(&attnB[q]);
    int e1 = e0 + half;
    bool v0 = e0 < ne;
    bool v1 = e1 < ne;
    int c0 = v0 ? e0 : 0;
    int c1 = v1 ? e1 : 0;
    int u0 = __ldg(&src[c0]), w0 = __ldg(&dst[c0]);
    int u1 = __ldg(&src[c1]), w1 = __ldg(&dst[c1]);
    edge_step(u0, w0, q, v0, fsA, fdA, aA, outA, denA);  // user -> item ('rate')
    edge_step(u1, w1, q, v1, fsA, fdA, aA, outA, denA);
    edge_step(w0, u0, q, v0, fsB, fdB, aB, outB, denB);  // item -> user ('rated-by')
    edge_step(w1, u1, q, v1, fsB, fdB, aB, outB, denB);
}

// ---------------- layer-2: rby (2 edges/thread) + trust (1 edge/thread) ------------
__global__ void edge_l2_kernel(
    const int* __restrict__ s1, const int* __restrict__ d1,
    const float4* __restrict__ fs1, const float4* __restrict__ fd1,
    const float4* __restrict__ a1, float* __restrict__ o1, float* __restrict__ den1,
    int ne1, int half1,
    const int* __restrict__ s2, const int* __restrict__ d2,
    const float4* __restrict__ fs2, const float4* __restrict__ fd2,
    const float4* __restrict__ a2, float* __restrict__ o2, float* __restrict__ den2,
    int ne2)
{
    int t = blockIdx.x * blockDim.x + threadIdx.x;
    int e0 = t >> 3;
    int q = t & 7;
    float4 aa1 = __ldg(&a1[q]);
    float4 aa2 = __ldg(&a2[q]);
    int e1 = e0 + half1;
    bool v0 = e0 < ne1;
    bool v1 = e1 < ne1;
    bool v2 = e0 < ne2;
    int c0 = v0 ? e0 : 0;
    int c1 = v1 ? e1 : 0;
    int c2 = v2 ? e0 : 0;
    int u0 = __ldg(&s1[c0]), w0 = __ldg(&d1[c0]);
    int u1 = __ldg(&s1[c1]), w1 = __ldg(&d1[c1]);
    int u2 = __ldg(&s2[c2]), w2 = __ldg(&d2[c2]);
    edge_step(u0, w0, q, v0, fs1, fd1, aa1, o1, den1);
    edge_step(u1, w1, q, v1, fs1, fd1, aa1, o1, den1);
    edge_step(u2, w2, q, v2, fs2, fd2, aa2, o2, den2);
}

// ---------------- output head + fused BN stats, persistent ----------------
__global__ void head_kernel(const float* __restrict__ A, const float* __restrict__ B,
                            const float* __restrict__ s3, const float* __restrict__ s4,
                            const float* __restrict__ Wout, const float* __restrict__ bout,
                            float* __restrict__ y, int nu) {
    __shared__ float WshA[32 * 36];   // Wout[out][0..31]
    __shared__ float WshB[32 * 36];   // Wout[out][32..63]
    __shared__ float ssum[32], ssq[32];
    int tid = threadIdx.x;
    for (int i = tid; i < 1024; i += blockDim.x) {
        int r = i >> 5, c = i & 31;
        WshA[r * 36 + c] = Wout[r * 64 + c];
        WshB[r * 36 + c] = Wout[r * 64 + 32 + c];
    }
    if (tid < 32) { ssum[tid] = 0.f; ssq[tid] = 0.f; }
    __syncthreads();
    int warp = tid >> 5, lane = tid & 31;
    float bias = bout[lane];
    float lsum = 0.f, lsq = 0.f;
    int rstep = gridDim.x * 8;
    for (int row = blockIdx.x * 8 + warp; row < nu; row += rstep) {
        float sa = s3[row]; sa = (sa > 0.f) ? (1.0f / sa) : 0.0f;
        float sb = s4[row]; sb = (sb > 0.f) ? (1.0f / sb) : 0.0f;
        float av = A[row * 32 + lane] * sa;
        float bv = B[row * 32 + lane] * sb;
        float acc = bias;
#pragma unroll
        for (int k = 0; k < 32; k += 4) {
            float a0 = __shfl_sync(0xffffffffu, av, k);
            float a1 = __shfl_sync(0xffffffffu, av, k + 1);
            float a2 = __shfl_sync(0xffffffffu, av, k + 2);
            float a3 = __shfl_sync(0xffffffffu, av, k + 3);
            float b0 = __shfl_sync(0xffffffffu, bv, k);
            float b1 = __shfl_sync(0xffffffffu, bv, k + 1);
            float b2 = __shfl_sync(0xffffffffu, bv, k + 2);
            float b3 = __shfl_sync(0xffffffffu, bv, k + 3);
            float4 wa = *(const float4*)&WshA[lane * 36 + k];
            float4 wb = *(const float4*)&WshB[lane * 36 + k];
            acc += a0 * wa.x + a1 * wa.y + a2 * wa.z + a3 * wa.w;
            acc += b0 * wb.x + b1 * wb.y + b2 * wb.z + b3 * wb.w;
        }
        y[row * 32 + lane] = acc;
        lsum += acc;
        lsq += acc * acc;
    }
    atomicAdd(&ssum[lane], lsum);
    atomicAdd(&ssq[lane], lsq);
    __syncthreads();
    if (tid < 32) {
        atomicAdd(&g_stats[tid], ssum[tid]);
        atomicAdd(&g_stats[32 + tid], ssq[tid]);
    }
}

// ---------------- finalize: BN + LeakyReLU(0.01) ----------------
__global__ void finalize_kernel(float* __restrict__ y, const float* __restrict__ gamma,
                                const float* __restrict__ beta, int nu) {
    int i = blockIdx.x * blockDim.x + threadIdx.x;
    if (i >= nu * 32) return;
    int c = i & 31;
    float inv_n = 1.0f / (float)nu;
    float mean = g_stats[c] * inv_n;
    float var = g_stats[32 + c] * inv_n - mean * mean;
    float v = (y[i] - mean) * rsqrtf(var + 1e-5f) * gamma[c] + beta[c];
    y[i] = (v > 0.f) ? v : 0.01f * v;
}

// ---------------- host launch ----------------
extern "C" void kernel_launch(void* const* d_in, const int* in_sizes, int n_in,
                              void* d_out, int out_size) {
    const float* user = (const float*)d_in[0];
    const float* item = (const float*)d_in[1];
    const int* rate_src  = (const int*)d_in[2];
    const int* rate_dst  = (const int*)d_in[3];
    const int* trust_src = (const int*)d_in[4];
    const int* trust_dst = (const int*)d_in[5];
    const float* p[20];
    for (int i = 0; i < 20; ++i) p[i] = (const float*)d_in[6 + i];
    const float* Wout  = (const float*)d_in[26];
    const float* bout  = (const float*)d_in[27];
    const float* gamma = (const float*)d_in[28];
    const float* beta  = (const float*)d_in[29];

    int nu = in_sizes[0] / EDIM;
    int ni = in_sizes[1] / EDIM;
    int ne_rate  = in_sizes[2];
    int ne_trust = in_sizes[4];
    float* y = (float*)d_out;

    float *U0, *U1, *U2, *U3, *I0, *I1, *P1, *P2, *H1, *H2, *A, *B, *S1, *S2, *S3, *S4;
    cudaGetSymbolAddress((void**)&U0, g_U0);
    cudaGetSymbolAddress((void**)&U1, g_U1);
    cudaGetSymbolAddress((void**)&U2, g_U2);
    cudaGetSymbolAddress((void**)&U3, g_U3);
    cudaGetSymbolAddress((void**)&I0, g_I0);
    cudaGetSymbolAddress((void**)&I1, g_I1);
    cudaGetSymbolAddress((void**)&P1, g_P1);
    cudaGetSymbolAddress((void**)&P2, g_P2);
    cudaGetSymbolAddress((void**)&H1, g_H1);
    cudaGetSymbolAddress((void**)&H2, g_H2);
    cudaGetSymbolAddress((void**)&A,  g_A);
    cudaGetSymbolAddress((void**)&B,  g_B);
    cudaGetSymbolAddress((void**)&S1, g_S1);
    cudaGetSymbolAddress((void**)&S2, g_S2);
    cudaGetSymbolAddress((void**)&S3, g_S3);
    cudaGetSymbolAddress((void**)&S4, g_S4);

    const int T = 256;
    int half_r = (ne_rate + 1) / 2;
    int gb_l1 = (half_r * 8 + T - 1) / T;
    int slots_l2 = (half_r > ne_trust) ? half_r : ne_trust;
    int gb_l2 = (slots_l2 * 8 + T - 1) / T;

    // persistent block counts (multiples of SM count 148)
    const int NBU = 592;   // user segment of proj_all (4 waves)
    const int NBI = 296;   // item segment of proj_all
    const int NBA = 296;   // projHH segment A (ni rows)
    const int NBB = 592;   // projHH segment B (nu rows)
    const int NBH = 592;   // head

    // all 6 input projections + scratch zeroing in one persistent segmented launch
    proj_all_kernel<<<NBU + NBI, T>>>(user, p[0], p[1], p[7], p[8], p[12], p[13], p[17], p[18],
                                      U0, U1, U2, U3, nu, NBU,
                                      item, p[2], p[3], p[5], p[6], I0, I1, ni);

    // layer 1 fused edge pass (rate + rated-by share the edge list), 2 edges/thread
    edge_l1_kernel<<<gb_l1, T>>>(rate_src, rate_dst,
                                 (const float4*)U0, (const float4*)I0, (const float4*)p[4], H1, S1,
                                 (const float4*)I1, (const float4*)U1, (const float4*)p[9], H2, S2,
                                 ne_rate, half_r);

    // layer-2 src projections (normalization folded via S1/S2), persistent
    projHH_kernel<<<NBA + NBB, T>>>(H1, S1, p[10], p[11], P1, ni, NBA,
                                    H2, S2, p[15], p[16], P2, nu);

    // layer-2 edge pass: rby (2 edges/thread) + trust (1 edge/thread)
    edge_l2_kernel<<<gb_l2, T>>>(
        rate_dst, rate_src, (const float4*)P1, (const float4*)U2, (const float4*)p[14], A, S3,
        ne_rate, half_r,
        trust_src, trust_dst, (const float4*)P2, (const float4*)U3, (const float4*)p[19], B, S4,
        ne_trust);

    // head (+fused BN stats) + finalize
    head_kernel<<<NBH, T>>>(A, B, S3, S4, Wout, bout, y, nu);
    finalize_kernel<<<(nu * EDIM + T - 1) / T, T>>>(y, gamma, beta, nu);
}